// round 3
// baseline (speedup 1.0000x reference)
#include <cuda_runtime.h>
#include <math.h>
#include <stdint.h>

#define HID   768
#define NH    12
#define DH    64
#define BATCH 4
#define SEQ   2048
#define MTOT  (BATCH*SEQ)   // 8192

// Scratch (allocation-free rule: __device__ globals)
__device__ float g_q[MTOT*HID];
__device__ float g_k[MTOT*HID];
__device__ float g_v[MTOT*HID];
__device__ float g_ctx[MTOT*HID];

// ---------------------------------------------------------------------------
__device__ __forceinline__ uint32_t f2tf(float x) {
    uint32_t r;
    asm("cvt.rna.tf32.f32 %0, %1;" : "=r"(r) : "f"(x));
    return r;
}

__device__ __forceinline__ void mma_tf32(float c[4],
    uint32_t a0, uint32_t a1, uint32_t a2, uint32_t a3,
    uint32_t b0, uint32_t b1)
{
    asm volatile(
        "mma.sync.aligned.m16n8k8.row.col.f32.tf32.tf32.f32 "
        "{%0,%1,%2,%3}, {%4,%5,%6,%7}, {%8,%9}, {%0,%1,%2,%3};"
        : "+f"(c[0]), "+f"(c[1]), "+f"(c[2]), "+f"(c[3])
        : "r"(a0), "r"(a1), "r"(a2), "r"(a3), "r"(b0), "r"(b1));
}

__device__ __forceinline__ uint2 pack2(float lo, float hi) {
    return make_uint2(f2tf(lo), f2tf(hi));
}

// ---------------------------------------------------------------------------
// GEMM: C[M,N] = A[M,K] @ W[K,N] + bias (+ exact GELU)
// BM=128, BN=64, BK=32. 256 thr / 8 warps (4x2), warp tile 32x32.
// Pair-interleaved smem (uint2 = {v[k], v[k+4]}), 2-stage double buffer.
// Smem (uint2): Ap[2][128][20], Bp[2][16][68]  -> 58368 B
// ---------------------------------------------------------------------------
#define G_APAD 20
#define G_BPAD 68
#define G_A_SZ (128*G_APAD)
#define G_B_SZ (16*G_BPAD)
#define G_SMEM_BYTES ((2*G_A_SZ + 2*G_B_SZ)*8)

template<bool GELU>
__global__ __launch_bounds__(256, 2) void gemm_tf32(
    const float* __restrict__ A, const float* __restrict__ W,
    const float* __restrict__ bias, float* __restrict__ C,
    int M, int K, int N)
{
    extern __shared__ uint2 sg[];
    uint2 (*Ap)[128][G_APAD] = (uint2(*)[128][G_APAD])(sg);
    uint2 (*Bp)[16][G_BPAD]  = (uint2(*)[16][G_BPAD])(sg + 2*G_A_SZ);

    const int tid  = threadIdx.x;
    const int lane = tid & 31;
    const int warp = tid >> 5;
    const int wm   = (warp >> 1) * 32;
    const int wn   = (warp & 1) * 32;
    const int m0   = blockIdx.y * 128;
    const int n0   = blockIdx.x * 64;
    const int c_   = lane & 3;
    const int q_   = lane >> 2;

    // producer indexing
    const int arow = tid >> 2;            // A: (row, ksi) group id low = tid&3
    const int aksi = tid & 3;
    const int brp  = tid >> 4;            // B: rowpair 0..15 (= ksi*4+c)
    const int bj   = tid & 15;            // col chunk
    const int bk_r = (brp >> 2) * 8 + (brp & 3);  // k-local row of .x

    float4 a_lo[2], a_hi[2], b_lo, b_hi;

    // --- load tile 0 ---
    {
        #pragma unroll
        for (int g = 0; g < 2; g++) {
            int row = arow + g * 64;
            const float* p = &A[(size_t)(m0 + row) * K + aksi * 8];
            a_lo[g] = *(const float4*)p;
            a_hi[g] = *(const float4*)(p + 4);
        }
        const float* p0 = &W[(size_t)(bk_r) * N + n0 + bj * 4];
        b_lo = *(const float4*)p0;
        b_hi = *(const float4*)(p0 + 4 * N);
    }

    float acc[2][4][4] = {};
    const int nT = K / 32;   // 24

    for (int t = 0; t < nT; t++) {
        const int buf = t & 1;
        // store staged regs -> smem[buf]
        #pragma unroll
        for (int g = 0; g < 2; g++) {
            int row = arow + g * 64;
            uint2* d = &Ap[buf][row][aksi * 4];
            d[0] = pack2(a_lo[g].x, a_hi[g].x);
            d[1] = pack2(a_lo[g].y, a_hi[g].y);
            d[2] = pack2(a_lo[g].z, a_hi[g].z);
            d[3] = pack2(a_lo[g].w, a_hi[g].w);
        }
        {
            uint2* d = &Bp[buf][brp][bj * 4];
            d[0] = pack2(b_lo.x, b_hi.x);
            d[1] = pack2(b_lo.y, b_hi.y);
            d[2] = pack2(b_lo.z, b_hi.z);
            d[3] = pack2(b_lo.w, b_hi.w);
        }
        __syncthreads();

        // prefetch tile t+1
        if (t + 1 < nT) {
            const int k0 = (t + 1) * 32;
            #pragma unroll
            for (int g = 0; g < 2; g++) {
                int row = arow + g * 64;
                const float* p = &A[(size_t)(m0 + row) * K + k0 + aksi * 8];
                a_lo[g] = *(const float4*)p;
                a_hi[g] = *(const float4*)(p + 4);
            }
            const float* p0 = &W[(size_t)(k0 + bk_r) * N + n0 + bj * 4];
            b_lo = *(const float4*)p0;
            b_hi = *(const float4*)(p0 + 4 * N);
        }

        // compute from smem[buf]
        #pragma unroll
        for (int ksi = 0; ksi < 4; ksi++) {
            uint2 a02[2], a13[2];
            #pragma unroll
            for (int mt = 0; mt < 2; mt++) {
                int r = wm + mt * 16 + q_;
                a02[mt] = Ap[buf][r    ][ksi * 4 + c_];
                a13[mt] = Ap[buf][r + 8][ksi * 4 + c_];
            }
            #pragma unroll
            for (int nt = 0; nt < 4; nt++) {
                uint2 bb = Bp[buf][ksi * 4 + c_][wn + nt * 8 + q_];
                mma_tf32(acc[0][nt], a02[0].x, a13[0].x, a02[0].y, a13[0].y, bb.x, bb.y);
                mma_tf32(acc[1][nt], a02[1].x, a13[1].x, a02[1].y, a13[1].y, bb.x, bb.y);
            }
        }
        __syncthreads();
    }

    #pragma unroll
    for (int mt = 0; mt < 2; mt++) {
        int r0 = m0 + wm + mt * 16 + q_;
        #pragma unroll
        for (int nt = 0; nt < 4; nt++) {
            int col = n0 + wn + nt * 8 + 2 * c_;
            float bv0 = bias[col], bv1 = bias[col + 1];
            float v0 = acc[mt][nt][0] + bv0;
            float v1 = acc[mt][nt][1] + bv1;
            float v2 = acc[mt][nt][2] + bv0;
            float v3 = acc[mt][nt][3] + bv1;
            if (GELU) {
                v0 *= normcdff(v0); v1 *= normcdff(v1);
                v2 *= normcdff(v2); v3 *= normcdff(v3);
            }
            *(float2*)&C[(size_t)r0       * N + col] = make_float2(v0, v1);
            *(float2*)&C[(size_t)(r0 + 8) * N + col] = make_float2(v2, v3);
        }
    }
}

// ---------------------------------------------------------------------------
// Flash attention, tf32 mma. Block = (b, h, 128-q-tile), 256 thr / 8 warps.
// Warp w owns q rows [w*16, w*16+16). K/V tiles of 64 streamed through smem.
// Pair-interleaved layouts; all fragment loads are LDS.64.
// Smem (uint2): Qp[128][36], Kp[64][36], Vp[32][68], Pp[128][36] + ms[64]f
// ---------------------------------------------------------------------------
#define A_QPAD 36
#define A_VPAD 68
#define A_Q_SZ (128*A_QPAD)
#define A_K_SZ (64*A_QPAD)
#define A_V_SZ (32*A_VPAD)
#define A_P_SZ (128*A_QPAD)
#define A_SMEM_BYTES ((A_Q_SZ + A_K_SZ + A_V_SZ + A_P_SZ)*8 + 64*4)

__global__ __launch_bounds__(256, 2) void attn_tf32(
    const float* __restrict__ qg, const float* __restrict__ kg,
    const float* __restrict__ vg, const float* __restrict__ mask,
    float* __restrict__ ctx)
{
    extern __shared__ uint2 sa[];
    uint2 (*Qp)[A_QPAD] = (uint2(*)[A_QPAD])(sa);
    uint2 (*Kp)[A_QPAD] = (uint2(*)[A_QPAD])(sa + A_Q_SZ);
    uint2 (*Vp)[A_VPAD] = (uint2(*)[A_VPAD])(sa + A_Q_SZ + A_K_SZ);
    uint2 (*Pp)[A_QPAD] = (uint2(*)[A_QPAD])(sa + A_Q_SZ + A_K_SZ + A_V_SZ);
    uint32_t* Pp32      = (uint32_t*)Pp;
    float* ms           = (float*)(sa + A_Q_SZ + A_K_SZ + A_V_SZ + A_P_SZ);

    const int tid  = threadIdx.x;
    const int lane = tid & 31;
    const int warp = tid >> 5;
    const int c_   = lane & 3;
    const int q_   = lane >> 2;
    const int b    = blockIdx.z;
    const int h    = blockIdx.y;
    const int q0   = blockIdx.x * 128;
    const int bS   = b * SEQ;
    const int hDH  = h * DH;
    const float scale = 0.125f;   // 1/sqrt(64)

    // ---- load Q tile (128x64) pair-interleaved: 4 (row,ksi) groups/thread
    #pragma unroll
    for (int g = 0; g < 4; g++) {
        int idx = tid + g * 256;
        int row = idx >> 3, ksi = idx & 7;
        const float* p = &qg[(size_t)(bS + q0 + row) * HID + hDH + ksi * 8];
        float4 lo = *(const float4*)p;
        float4 hi = *(const float4*)(p + 4);
        uint2* d = &Qp[row][ksi * 4];
        d[0] = pack2(lo.x, hi.x); d[1] = pack2(lo.y, hi.y);
        d[2] = pack2(lo.z, hi.z); d[3] = pack2(lo.w, hi.w);
    }

    const int rw   = warp * 16 + q_;   // this thread's row (first of pair)
    const float mq0 = mask[bS + q0 + rw];
    const float mq1 = mask[bS + q0 + rw + 8];

    float mrow0 = -1e30f, mrow1 = -1e30f, l0 = 0.0f, l1 = 0.0f;
    float o[8][4] = {};

    for (int kt = 0; kt < SEQ / 64; kt++) {
        const int k0 = kt * 64;

        // ---- K producer: 2 (row,ksi) groups/thread
        #pragma unroll
        for (int g = 0; g < 2; g++) {
            int idx = tid + g * 256;
            int row = idx >> 3, ksi = idx & 7;
            const float* p = &kg[(size_t)(bS + k0 + row) * HID + hDH + ksi * 8];
            float4 lo = *(const float4*)p;
            float4 hi = *(const float4*)(p + 4);
            uint2* d = &Kp[row][ksi * 4];
            d[0] = pack2(lo.x, hi.x); d[1] = pack2(lo.y, hi.y);
            d[2] = pack2(lo.z, hi.z); d[3] = pack2(lo.w, hi.w);
        }
        // ---- V producer: rows paired (k, k+4); 2 (rp,j) groups/thread
        #pragma unroll
        for (int g = 0; g < 2; g++) {
            int idx = tid + g * 256;
            int rp = idx >> 4, j = idx & 15;           // rp = ksi*4+c
            int krow = (rp >> 2) * 8 + (rp & 3);       // k-local of .x
            const float* p0 = &vg[(size_t)(bS + k0 + krow) * HID + hDH + j * 4];
            float4 lo = *(const float4*)p0;
            float4 hi = *(const float4*)(p0 + 4 * HID);  // row +4
            uint2* d = &Vp[rp][j * 4];
            d[0] = pack2(lo.x, hi.x); d[1] = pack2(lo.y, hi.y);
            d[2] = pack2(lo.z, hi.z); d[3] = pack2(lo.w, hi.w);
        }
        if (tid < 64) ms[tid] = mask[bS + k0 + tid];
        __syncthreads();

        // ---- S = Q K^T (warp: 16x64)
        float s[8][4] = {};
        #pragma unroll
        for (int ksi = 0; ksi < 8; ksi++) {
            uint2 a02 = Qp[rw    ][ksi * 4 + c_];
            uint2 a13 = Qp[rw + 8][ksi * 4 + c_];
            #pragma unroll
            for (int nt = 0; nt < 8; nt++) {
                uint2 bb = Kp[nt * 8 + q_][ksi * 4 + c_];
                mma_tf32(s[nt], a02.x, a13.x, a02.y, a13.y, bb.x, bb.y);
            }
        }

        // ---- scale + mask: ext*s - (1-ext)*1e9
        #pragma unroll
        for (int nt = 0; nt < 8; nt++) {
            float mk0 = ms[nt * 8 + 2 * c_];
            float mk1 = ms[nt * 8 + 2 * c_ + 1];
            float e;
            e = mq0 * mk0; s[nt][0] = e * (s[nt][0] * scale) - (1.0f - e) * 1e9f;
            e = mq0 * mk1; s[nt][1] = e * (s[nt][1] * scale) - (1.0f - e) * 1e9f;
            e = mq1 * mk0; s[nt][2] = e * (s[nt][2] * scale) - (1.0f - e) * 1e9f;
            e = mq1 * mk1; s[nt][3] = e * (s[nt][3] * scale) - (1.0f - e) * 1e9f;
        }

        // ---- online softmax (rows in 4-lane groups -> xor 1,2)
        float tm0 = -1e30f, tm1 = -1e30f;
        #pragma unroll
        for (int nt = 0; nt < 8; nt++) {
            tm0 = fmaxf(tm0, fmaxf(s[nt][0], s[nt][1]));
            tm1 = fmaxf(tm1, fmaxf(s[nt][2], s[nt][3]));
        }
        tm0 = fmaxf(tm0, __shfl_xor_sync(0xffffffffu, tm0, 1));
        tm0 = fmaxf(tm0, __shfl_xor_sync(0xffffffffu, tm0, 2));
        tm1 = fmaxf(tm1, __shfl_xor_sync(0xffffffffu, tm1, 1));
        tm1 = fmaxf(tm1, __shfl_xor_sync(0xffffffffu, tm1, 2));

        float mn0 = fmaxf(mrow0, tm0), mn1 = fmaxf(mrow1, tm1);
        float al0 = __expf(mrow0 - mn0), al1 = __expf(mrow1 - mn1);
        float rs0 = 0.0f, rs1 = 0.0f;
        #pragma unroll
        for (int nt = 0; nt < 8; nt++) {
            s[nt][0] = __expf(s[nt][0] - mn0); rs0 += s[nt][0];
            s[nt][1] = __expf(s[nt][1] - mn0); rs0 += s[nt][1];
            s[nt][2] = __expf(s[nt][2] - mn1); rs1 += s[nt][2];
            s[nt][3] = __expf(s[nt][3] - mn1); rs1 += s[nt][3];
        }
        rs0 += __shfl_xor_sync(0xffffffffu, rs0, 1);
        rs0 += __shfl_xor_sync(0xffffffffu, rs0, 2);
        rs1 += __shfl_xor_sync(0xffffffffu, rs1, 1);
        rs1 += __shfl_xor_sync(0xffffffffu, rs1, 2);

        l0 = l0 * al0 + rs0;  l1 = l1 * al1 + rs1;
        mrow0 = mn0;  mrow1 = mn1;
        #pragma unroll
        for (int nt = 0; nt < 8; nt++) {
            o[nt][0] *= al0; o[nt][1] *= al0;
            o[nt][2] *= al1; o[nt][3] *= al1;
        }

        // ---- P -> smem (pair-interleaved, warp-private rows)
        {
            // C-frag cols j0=2c_, j0+1 within each 8-chunk; h = j0>>2, cc = j0&3
            const int hh = (2 * c_) >> 2;          // 0 or 1
            const int cc = (2 * c_) & 3;           // 0 or 2
            const int stride = A_QPAD * 2;         // uint32 per row
            uint32_t* pr0 = &Pp32[rw * stride + hh];
            uint32_t* pr1 = &Pp32[(rw + 8) * stride + hh];
            #pragma unroll
            for (int nt = 0; nt < 8; nt++) {
                int base = (nt * 4 + cc) * 2;
                pr0[base]     = f2tf(s[nt][0]);
                pr0[base + 2] = f2tf(s[nt][1]);
                pr1[base]     = f2tf(s[nt][2]);
                pr1[base + 2] = f2tf(s[nt][3]);
            }
        }
        __syncwarp();

        // ---- O += P V (warp: 16x64)
        #pragma unroll
        for (int ksi = 0; ksi < 8; ksi++) {
            uint2 a02 = Pp[rw    ][ksi * 4 + c_];
            uint2 a13 = Pp[rw + 8][ksi * 4 + c_];
            #pragma unroll
            for (int nt = 0; nt < 8; nt++) {
                uint2 bb = Vp[ksi * 4 + c_][nt * 8 + q_];
                mma_tf32(o[nt], a02.x, a13.x, a02.y, a13.y, bb.x, bb.y);
            }
        }
        __syncthreads();   // protect Kp/Vp/ms before next producer pass
    }

    // ---- epilogue
    float inv0 = 1.0f / l0, inv1 = 1.0f / l1;
    int gr = bS + q0 + rw;
    #pragma unroll
    for (int nt = 0; nt < 8; nt++) {
        int col = hDH + nt * 8 + 2 * c_;
        *(float2*)&ctx[(size_t)gr       * HID + col] = make_float2(o[nt][0] * inv0, o[nt][1] * inv0);
        *(float2*)&ctx[(size_t)(gr + 8) * HID + col] = make_float2(o[nt][2] * inv1, o[nt][3] * inv1);
    }
}

// ---------------------------------------------------------------------------
extern "C" void kernel_launch(void* const* d_in, const int* in_sizes, int n_in,
                              void* d_out, int out_size)
{
    const float* hs   = (const float*)d_in[0];
    const float* mask = (const float*)d_in[1];
    const float* Wq   = (const float*)d_in[2];
    const float* bq   = (const float*)d_in[3];
    const float* Wk   = (const float*)d_in[4];
    const float* bk   = (const float*)d_in[5];
    const float* Wv   = (const float*)d_in[6];
    const float* bv   = (const float*)d_in[7];
    const float* Wo   = (const float*)d_in[8];
    const float* bo   = (const float*)d_in[9];
    float* out = (float*)d_out;

    float *qb, *kb, *vb, *cb;
    cudaGetSymbolAddress((void**)&qb, g_q);
    cudaGetSymbolAddress((void**)&kb, g_k);
    cudaGetSymbolAddress((void**)&vb, g_v);
    cudaGetSymbolAddress((void**)&cb, g_ctx);

    cudaFuncSetAttribute(gemm_tf32<false>, cudaFuncAttributeMaxDynamicSharedMemorySize, G_SMEM_BYTES);
    cudaFuncSetAttribute(gemm_tf32<true>,  cudaFuncAttributeMaxDynamicSharedMemorySize, G_SMEM_BYTES);
    cudaFuncSetAttribute(attn_tf32, cudaFuncAttributeMaxDynamicSharedMemorySize, A_SMEM_BYTES);

    dim3 ggrid(HID / 64, MTOT / 128);   // (12, 64)
    gemm_tf32<false><<<ggrid, 256, G_SMEM_BYTES>>>(hs, Wq, bq, qb, MTOT, HID, HID);
    gemm_tf32<false><<<ggrid, 256, G_SMEM_BYTES>>>(hs, Wk, bk, kb, MTOT, HID, HID);
    gemm_tf32<false><<<ggrid, 256, G_SMEM_BYTES>>>(hs, Wv, bv, vb, MTOT, HID, HID);

    dim3 agrid(SEQ / 128, NH, BATCH);   // (16, 12, 4)
    attn_tf32<<<agrid, 256, A_SMEM_BYTES>>>(qb, kb, vb, mask, cb);

    gemm_tf32<true><<<ggrid, 256, G_SMEM_BYTES>>>(cb, Wo, bo, out, MTOT, HID, HID);
}

// round 4
// speedup vs baseline: 1.1005x; 1.1005x over previous
#include <cuda_runtime.h>
#include <math.h>
#include <stdint.h>

#define HID   768
#define NH    12
#define DH    64
#define BATCH 4
#define SEQ   2048
#define MTOT  (BATCH*SEQ)   // 8192

// Scratch (allocation-free rule: __device__ globals)
__device__ float g_hsr[MTOT*HID];        // hs rounded to tf32
__device__ float g_wr[4][HID*HID];       // Wq,Wk,Wv,Wo rounded
__device__ float g_qh[MTOT*HID];         // q head-major rounded
__device__ float g_kh[MTOT*HID];
__device__ float g_vh[MTOT*HID];
__device__ float g_ctx[MTOT*HID];        // ctx standard layout, rounded

// ---------------------------------------------------------------------------
__device__ __forceinline__ uint32_t f2tf(float x) {
    uint32_t r;
    asm("cvt.rna.tf32.f32 %0, %1;" : "=r"(r) : "f"(x));
    return r;
}
__device__ __forceinline__ float f2tf_f(float x) { 
    uint32_t u = f2tf(x); return __uint_as_float(u);
}

__device__ __forceinline__ void mma_tf32(float c[4],
    uint32_t a0, uint32_t a1, uint32_t a2, uint32_t a3,
    uint32_t b0, uint32_t b1)
{
    asm volatile(
        "mma.sync.aligned.m16n8k8.row.col.f32.tf32.tf32.f32 "
        "{%0,%1,%2,%3}, {%4,%5,%6,%7}, {%8,%9}, {%0,%1,%2,%3};"
        : "+f"(c[0]), "+f"(c[1]), "+f"(c[2]), "+f"(c[3])
        : "r"(a0), "r"(a1), "r"(a2), "r"(a3), "r"(b0), "r"(b1));
}

__device__ __forceinline__ uint32_t smaddr(const void* p) {
    return (uint32_t)__cvta_generic_to_shared(p);
}
__device__ __forceinline__ void cpa16(uint32_t dst, const void* src) {
    asm volatile("cp.async.cg.shared.global [%0], [%1], 16;" :: "r"(dst), "l"(src));
}
__device__ __forceinline__ void cpa_commit() {
    asm volatile("cp.async.commit_group;" ::: "memory");
}
__device__ __forceinline__ void cpa_wait1() {
    asm volatile("cp.async.wait_group 1;" ::: "memory");
}

// ---------------------------------------------------------------------------
// Pre-round a buffer to tf32 (float4 grid-stride)
// ---------------------------------------------------------------------------
__global__ void round_k(const float* __restrict__ in, float* __restrict__ out, int n4)
{
    int i = blockIdx.x * blockDim.x + threadIdx.x;
    if (i < n4) {
        float4 v = ((const float4*)in)[i];
        float4 r = make_float4(f2tf_f(v.x), f2tf_f(v.y), f2tf_f(v.z), f2tf_f(v.w));
        ((float4*)out)[i] = r;
    }
}

// ---------------------------------------------------------------------------
// GEMM: C = A[M,768] @ W[768,768] + bias. Inputs pre-rounded tf32.
// BM=128, BN=64, BK=32, 256 thr / 8 warps (4x2), warp tile 32x32.
// cp.async 2-stage double buffer. Dynamic smem:
//   As[2][128][36] + Bs[2][32][68]  = 54272 B
// HEADM: write to head-major scratch rounded. GELU: bias+gelu raw f32.
// ---------------------------------------------------------------------------
#define G_AS (128*36)
#define G_BS (32*68)
#define G_SMEM_BYTES ((2*G_AS + 2*G_BS)*4)

template<bool GELU, bool HEADM>
__global__ __launch_bounds__(256, 3) void gemm2(
    const float* __restrict__ A, const float* __restrict__ W,
    const float* __restrict__ bias, float* __restrict__ C)
{
    extern __shared__ float sg[];
    float* Asm = sg;                 // [2][128][36]
    float* Bsm = sg + 2 * G_AS;      // [2][32][68]

    const int tid  = threadIdx.x;
    const int lane = tid & 31;
    const int warp = tid >> 5;
    const int wm   = (warp >> 1) * 32;
    const int wn   = (warp & 1) * 32;
    const int m0   = blockIdx.y * 128;
    const int n0   = blockIdx.x * 64;
    const int c_   = lane & 3;
    const int q_   = lane >> 2;

    const int ar = tid >> 3, ac = (tid & 7) * 4;       // A: 4 chunks (rows +0,+32,+64,+96? no: idx scheme)
    const int br = tid >> 4, bc = (tid & 15) * 4;

    float acc[2][4][4] = {};
    const int nT = HID / 32;   // 24

    // prologue: tile 0 -> buf 0
    {
        #pragma unroll
        for (int i = 0; i < 4; i++) {
            int row = ar + i * 32;
            cpa16(smaddr(&Asm[row * 36 + ac]), &A[(size_t)(m0 + row) * HID + ac]);
        }
        #pragma unroll
        for (int i = 0; i < 2; i++) {
            int row = br + i * 16;
            cpa16(smaddr(&Bsm[row * 68 + bc]), &W[(size_t)row * HID + n0 + bc]);
        }
        cpa_commit();
    }

    for (int t = 0; t < nT; t++) {
        const int cur = t & 1;
        if (t + 1 < nT) {
            const int k0 = (t + 1) * 32;
            float* Ad = Asm + (cur ^ 1) * G_AS;
            float* Bd = Bsm + (cur ^ 1) * G_BS;
            #pragma unroll
            for (int i = 0; i < 4; i++) {
                int row = ar + i * 32;
                cpa16(smaddr(&Ad[row * 36 + ac]), &A[(size_t)(m0 + row) * HID + k0 + ac]);
            }
            #pragma unroll
            for (int i = 0; i < 2; i++) {
                int row = br + i * 16;
                cpa16(smaddr(&Bd[row * 68 + bc]), &W[(size_t)(k0 + row) * HID + n0 + bc]);
            }
        }
        cpa_commit();
        cpa_wait1();
        __syncthreads();

        const float* Ac = Asm + cur * G_AS;
        const float* Bc = Bsm + cur * G_BS;
        #pragma unroll
        for (int ksi = 0; ksi < 4; ksi++) {
            uint32_t a[2][4];
            #pragma unroll
            for (int mt = 0; mt < 2; mt++) {
                int r = wm + mt * 16 + q_;
                a[mt][0] = __float_as_uint(Ac[r * 36 + ksi * 8 + c_]);
                a[mt][1] = __float_as_uint(Ac[(r + 8) * 36 + ksi * 8 + c_]);
                a[mt][2] = __float_as_uint(Ac[r * 36 + ksi * 8 + c_ + 4]);
                a[mt][3] = __float_as_uint(Ac[(r + 8) * 36 + ksi * 8 + c_ + 4]);
            }
            #pragma unroll
            for (int nt = 0; nt < 4; nt++) {
                uint32_t b0 = __float_as_uint(Bc[(ksi * 8 + c_) * 68 + wn + nt * 8 + q_]);
                uint32_t b1 = __float_as_uint(Bc[(ksi * 8 + c_ + 4) * 68 + wn + nt * 8 + q_]);
                mma_tf32(acc[0][nt], a[0][0], a[0][1], a[0][2], a[0][3], b0, b1);
                mma_tf32(acc[1][nt], a[1][0], a[1][1], a[1][2], a[1][3], b0, b1);
            }
        }
        __syncthreads();
    }

    // epilogue
    #pragma unroll
    for (int mt = 0; mt < 2; mt++) {
        int r0 = m0 + wm + mt * 16 + q_;
        #pragma unroll
        for (int nt = 0; nt < 4; nt++) {
            int col = n0 + wn + nt * 8 + 2 * c_;
            float bv0 = bias[col], bv1 = bias[col + 1];
            float v0 = acc[mt][nt][0] + bv0;
            float v1 = acc[mt][nt][1] + bv1;
            float v2 = acc[mt][nt][2] + bv0;
            float v3 = acc[mt][nt][3] + bv1;
            if (GELU) {
                v0 *= normcdff(v0); v1 *= normcdff(v1);
                v2 *= normcdff(v2); v3 *= normcdff(v3);
                *(float2*)&C[(size_t)r0       * HID + col] = make_float2(v0, v1);
                *(float2*)&C[(size_t)(r0 + 8) * HID + col] = make_float2(v2, v3);
            } else if (HEADM) {
                // head-major: ((b*NH+h)*SEQ + s)*64 + d, rounded
                int h = col >> 6, d = col & 63;
                int b0r = r0 >> 11, s0 = r0 & 2047;
                size_t dst0 = ((size_t)(b0r * NH + h) * SEQ + s0) * 64 + d;
                size_t dst1 = dst0 + 8 * 64;   // row r0+8, same b (128-row tile within batch)
                *(float2*)&C[dst0] = make_float2(f2tf_f(v0), f2tf_f(v1));
                *(float2*)&C[dst1] = make_float2(f2tf_f(v2), f2tf_f(v3));
            } else {
                *(float2*)&C[(size_t)r0       * HID + col] = make_float2(f2tf_f(v0), f2tf_f(v1));
                *(float2*)&C[(size_t)(r0 + 8) * HID + col] = make_float2(f2tf_f(v2), f2tf_f(v3));
            }
        }
    }
}

// ---------------------------------------------------------------------------
// Flash attention. Block = (b, h, 64-q-tile), 128 thr / 4 warps.
// Q fragments in registers. K/V double-buffered via cp.async from head-major
// pre-rounded scratch. P aliased into the spent K compute buffer.
// Dynamic smem: K[2][64][68] + V[2][64][68] + ms[2][64] = 70144 B -> 3 CTA/SM
// ---------------------------------------------------------------------------
#define A_TS (64*68)
#define A_SMEM_BYTES ((4*A_TS + 128)*4)

__global__ __launch_bounds__(128, 3) void attn2(
    const float* __restrict__ qh, const float* __restrict__ kh,
    const float* __restrict__ vh, const float* __restrict__ mask,
    float* __restrict__ ctx)
{
    extern __shared__ float sa[];
    float* msb = sa + 4 * A_TS;   // [2][64]

    const int tid  = threadIdx.x;
    const int lane = tid & 31;
    const int warp = tid >> 5;
    const int c_   = lane & 3;
    const int q_   = lane >> 2;
    const int b    = blockIdx.z;
    const int h    = blockIdx.y;
    const int q0   = blockIdx.x * 64;
    const int bS   = b * SEQ;
    const int bh   = b * NH + h;
    const float scale = 0.125f;   // 1/sqrt(64)

    const int prow = tid >> 4;          // producer row 0..7 (+8k)
    const int pch  = (tid & 15) * 4;    // producer col chunk

    const float* kbase0 = &kh[(size_t)bh * SEQ * 64];
    const float* vbase0 = &vh[(size_t)bh * SEQ * 64];

    // prologue: tile 0 -> buf 0
    {
        #pragma unroll
        for (int i = 0; i < 8; i++) {
            int row = prow + i * 8;
            cpa16(smaddr(&sa[0 * A_TS + row * 68 + pch]), kbase0 + (size_t)row * 64 + pch);
            cpa16(smaddr(&sa[2 * A_TS + row * 68 + pch]), vbase0 + (size_t)row * 64 + pch);
        }
        if (tid < 16) cpa16(smaddr(&msb[tid * 4]), &mask[bS + tid * 4]);
        cpa_commit();
    }

    // Q fragments in registers (whole loop)
    const int rw = warp * 16 + q_;
    uint32_t qa[8][4];
    {
        const float* p0 = &qh[((size_t)bh * SEQ + q0 + rw) * 64];
        const float* p1 = p0 + 8 * 64;
        #pragma unroll
        for (int ksi = 0; ksi < 8; ksi++) {
            qa[ksi][0] = __float_as_uint(p0[ksi * 8 + c_]);
            qa[ksi][1] = __float_as_uint(p1[ksi * 8 + c_]);
            qa[ksi][2] = __float_as_uint(p0[ksi * 8 + c_ + 4]);
            qa[ksi][3] = __float_as_uint(p1[ksi * 8 + c_ + 4]);
        }
    }
    const float mq0 = mask[bS + q0 + rw];
    const float mq1 = mask[bS + q0 + rw + 8];

    float mrow0 = -1e30f, mrow1 = -1e30f, l0 = 0.0f, l1 = 0.0f;
    float o[8][4] = {};

    const int nT = SEQ / 64;   // 32
    for (int t = 0; t < nT; t++) {
        const int cur = t & 1;
        if (t + 1 < nT) {
            const int k0 = (t + 1) * 64;
            float* Kd = sa + (cur ^ 1) * A_TS;
            float* Vd = sa + (2 + (cur ^ 1)) * A_TS;
            const float* kb = kbase0 + (size_t)k0 * 64;
            const float* vb = vbase0 + (size_t)k0 * 64;
            #pragma unroll
            for (int i = 0; i < 8; i++) {
                int row = prow + i * 8;
                cpa16(smaddr(&Kd[row * 68 + pch]), kb + (size_t)row * 64 + pch);
                cpa16(smaddr(&Vd[row * 68 + pch]), vb + (size_t)row * 64 + pch);
            }
            if (tid < 16) cpa16(smaddr(&msb[(cur ^ 1) * 64 + tid * 4]), &mask[bS + k0 + tid * 4]);
        }
        cpa_commit();
        cpa_wait1();
        __syncthreads();

        float* Kc = sa + cur * A_TS;
        float* Vc = sa + (2 + cur) * A_TS;
        const float* mc = msb + cur * 64;

        // ---- S = Q K^T (warp: 16x64)
        float s[8][4] = {};
        #pragma unroll
        for (int ksi = 0; ksi < 8; ksi++) {
            #pragma unroll
            for (int nt = 0; nt < 8; nt++) {
                uint32_t b0 = __float_as_uint(Kc[(nt * 8 + q_) * 68 + ksi * 8 + c_]);
                uint32_t b1 = __float_as_uint(Kc[(nt * 8 + q_) * 68 + ksi * 8 + c_ + 4]);
                mma_tf32(s[nt], qa[ksi][0], qa[ksi][1], qa[ksi][2], qa[ksi][3], b0, b1);
            }
        }

        // ---- scale + mask
        #pragma unroll
        for (int nt = 0; nt < 8; nt++) {
            float mk0 = mc[nt * 8 + 2 * c_];
            float mk1 = mc[nt * 8 + 2 * c_ + 1];
            float e;
            e = mq0 * mk0; s[nt][0] = e * (s[nt][0] * scale) - (1.0f - e) * 1e9f;
            e = mq0 * mk1; s[nt][1] = e * (s[nt][1] * scale) - (1.0f - e) * 1e9f;
            e = mq1 * mk0; s[nt][2] = e * (s[nt][2] * scale) - (1.0f - e) * 1e9f;
            e = mq1 * mk1; s[nt][3] = e * (s[nt][3] * scale) - (1.0f - e) * 1e9f;
        }

        // ---- online softmax (rows in 4-lane groups -> xor 1,2)
        float tm0 = -1e30f, tm1 = -1e30f;
        #pragma unroll
        for (int nt = 0; nt < 8; nt++) {
            tm0 = fmaxf(tm0, fmaxf(s[nt][0], s[nt][1]));
            tm1 = fmaxf(tm1, fmaxf(s[nt][2], s[nt][3]));
        }
        tm0 = fmaxf(tm0, __shfl_xor_sync(0xffffffffu, tm0, 1));
        tm0 = fmaxf(tm0, __shfl_xor_sync(0xffffffffu, tm0, 2));
        tm1 = fmaxf(tm1, __shfl_xor_sync(0xffffffffu, tm1, 1));
        tm1 = fmaxf(tm1, __shfl_xor_sync(0xffffffffu, tm1, 2));

        float mn0 = fmaxf(mrow0, tm0), mn1 = fmaxf(mrow1, tm1);
        float al0 = __expf(mrow0 - mn0), al1 = __expf(mrow1 - mn1);
        float rs0 = 0.0f, rs1 = 0.0f;
        #pragma unroll
        for (int nt = 0; nt < 8; nt++) {
            s[nt][0] = __expf(s[nt][0] - mn0); rs0 += s[nt][0];
            s[nt][1] = __expf(s[nt][1] - mn0); rs0 += s[nt][1];
            s[nt][2] = __expf(s[nt][2] - mn1); rs1 += s[nt][2];
            s[nt][3] = __expf(s[nt][3] - mn1); rs1 += s[nt][3];
        }
        rs0 += __shfl_xor_sync(0xffffffffu, rs0, 1);
        rs0 += __shfl_xor_sync(0xffffffffu, rs0, 2);
        rs1 += __shfl_xor_sync(0xffffffffu, rs1, 1);
        rs1 += __shfl_xor_sync(0xffffffffu, rs1, 2);

        l0 = l0 * al0 + rs0;  l1 = l1 * al1 + rs1;
        mrow0 = mn0;  mrow1 = mn1;
        #pragma unroll
        for (int nt = 0; nt < 8; nt++) {
            o[nt][0] *= al0; o[nt][1] *= al0;
            o[nt][2] *= al1; o[nt][3] *= al1;
        }

        __syncthreads();   // all warps done reading Kc -> safe to overwrite with P

        // ---- P -> Kc (tf32 bits), rows warp-private
        #pragma unroll
        for (int nt = 0; nt < 8; nt++) {
            *(uint2*)&Kc[rw * 68 + nt * 8 + 2 * c_] =
                make_uint2(f2tf(s[nt][0]), f2tf(s[nt][1]));
            *(uint2*)&Kc[(rw + 8) * 68 + nt * 8 + 2 * c_] =
                make_uint2(f2tf(s[nt][2]), f2tf(s[nt][3]));
        }
        __syncwarp();

        // ---- O += P V (warp: 16x64)
        #pragma unroll
        for (int ksi = 0; ksi < 8; ksi++) {
            uint32_t a0 = __float_as_uint(Kc[rw * 68 + ksi * 8 + c_]);
            uint32_t a1 = __float_as_uint(Kc[(rw + 8) * 68 + ksi * 8 + c_]);
            uint32_t a2 = __float_as_uint(Kc[rw * 68 + ksi * 8 + c_ + 4]);
            uint32_t a3 = __float_as_uint(Kc[(rw + 8) * 68 + ksi * 8 + c_ + 4]);
            #pragma unroll
            for (int nt = 0; nt < 8; nt++) {
                uint32_t b0 = __float_as_uint(Vc[(ksi * 8 + c_) * 68 + nt * 8 + q_]);
                uint32_t b1 = __float_as_uint(Vc[(ksi * 8 + c_ + 4) * 68 + nt * 8 + q_]);
                mma_tf32(o[nt], a0, a1, a2, a3, b0, b1);
            }
        }
        __syncthreads();   // done with Kc (P) and Vc before next produce overwrites
    }

    // ---- epilogue: normalize, write rounded ctx (standard layout)
    float inv0 = 1.0f / l0, inv1 = 1.0f / l1;
    int gr = bS + q0 + rw;
    #pragma unroll
    for (int nt = 0; nt < 8; nt++) {
        int col = h * DH + nt * 8 + 2 * c_;
        *(float2*)&ctx[(size_t)gr * HID + col] =
            make_float2(f2tf_f(o[nt][0] * inv0), f2tf_f(o[nt][1] * inv0));
        *(float2*)&ctx[(size_t)(gr + 8) * HID + col] =
            make_float2(f2tf_f(o[nt][2] * inv1), f2tf_f(o[nt][3] * inv1));
    }
}

// ---------------------------------------------------------------------------
extern "C" void kernel_launch(void* const* d_in, const int* in_sizes, int n_in,
                              void* d_out, int out_size)
{
    const float* hs   = (const float*)d_in[0];
    const float* mask = (const float*)d_in[1];
    const float* Wq   = (const float*)d_in[2];
    const float* bq   = (const float*)d_in[3];
    const float* Wk   = (const float*)d_in[4];
    const float* bk   = (const float*)d_in[5];
    const float* Wv   = (const float*)d_in[6];
    const float* bv   = (const float*)d_in[7];
    const float* Wo   = (const float*)d_in[8];
    const float* bo   = (const float*)d_in[9];
    float* out = (float*)d_out;

    float *hsr, *wr, *qh, *kh, *vh, *cb;
    cudaGetSymbolAddress((void**)&hsr, g_hsr);
    cudaGetSymbolAddress((void**)&wr,  g_wr);
    cudaGetSymbolAddress((void**)&qh,  g_qh);
    cudaGetSymbolAddress((void**)&kh,  g_kh);
    cudaGetSymbolAddress((void**)&vh,  g_vh);
    cudaGetSymbolAddress((void**)&cb,  g_ctx);

    cudaFuncSetAttribute(gemm2<false,true>,  cudaFuncAttributeMaxDynamicSharedMemorySize, G_SMEM_BYTES);
    cudaFuncSetAttribute(gemm2<true,false>,  cudaFuncAttributeMaxDynamicSharedMemorySize, G_SMEM_BYTES);
    cudaFuncSetAttribute(attn2, cudaFuncAttributeMaxDynamicSharedMemorySize, A_SMEM_BYTES);

    // --- pre-round inputs to tf32 ---
    const int WN4 = HID * HID / 4;
    round_k<<<(MTOT * HID / 4 + 255) / 256, 256>>>(hs, hsr, MTOT * HID / 4);
    round_k<<<(WN4 + 255) / 256, 256>>>(Wq, wr + 0 * HID * HID, WN4);
    round_k<<<(WN4 + 255) / 256, 256>>>(Wk, wr + 1 * HID * HID, WN4);
    round_k<<<(WN4 + 255) / 256, 256>>>(Wv, wr + 2 * HID * HID, WN4);
    round_k<<<(WN4 + 255) / 256, 256>>>(Wo, wr + 3 * HID * HID, WN4);

    // --- projections (write head-major rounded) ---
    dim3 ggrid(HID / 64, MTOT / 128);   // (12, 64)
    gemm2<false,true><<<ggrid, 256, G_SMEM_BYTES>>>(hsr, wr + 0 * HID * HID, bq, qh);
    gemm2<false,true><<<ggrid, 256, G_SMEM_BYTES>>>(hsr, wr + 1 * HID * HID, bk, kh);
    gemm2<false,true><<<ggrid, 256, G_SMEM_BYTES>>>(hsr, wr + 2 * HID * HID, bv, vh);

    // --- attention ---
    dim3 agrid(SEQ / 64, NH, BATCH);    // (32, 12, 4)
    attn2<<<agrid, 128, A_SMEM_BYTES>>>(qh, kh, vh, mask, cb);

    // --- output projection + GELU ---
    gemm2<true,false><<<ggrid, 256, G_SMEM_BYTES>>>(cb, wr + 3 * HID * HID, bo, out);
}

// round 5
// speedup vs baseline: 1.3751x; 1.2495x over previous
#include <cuda_runtime.h>
#include <math.h>
#include <stdint.h>

#define HID   768
#define NH    12
#define DH    64
#define BATCH 4
#define SEQ   2048
#define MTOT  (BATCH*SEQ)   // 8192

// Scratch (allocation-free rule: __device__ globals)
__device__ float g_hsr[MTOT*HID];        // hs rounded to tf32
__device__ float g_wr[4][HID*HID];       // Wq,Wk,Wv,Wo rounded
__device__ float g_qh[MTOT*HID];         // q head-major rounded
__device__ float g_kh[MTOT*HID];
__device__ float g_vh[MTOT*HID];
__device__ float g_ctx[MTOT*HID];        // ctx standard layout, rounded

// ---------------------------------------------------------------------------
__device__ __forceinline__ uint32_t f2tf(float x) {
    uint32_t r;
    asm("cvt.rna.tf32.f32 %0, %1;" : "=r"(r) : "f"(x));
    return r;
}
__device__ __forceinline__ float f2tf_f(float x) {
    uint32_t u = f2tf(x); return __uint_as_float(u);
}

__device__ __forceinline__ void mma_tf32(float c[4],
    uint32_t a0, uint32_t a1, uint32_t a2, uint32_t a3,
    uint32_t b0, uint32_t b1)
{
    asm volatile(
        "mma.sync.aligned.m16n8k8.row.col.f32.tf32.tf32.f32 "
        "{%0,%1,%2,%3}, {%4,%5,%6,%7}, {%8,%9}, {%0,%1,%2,%3};"
        : "+f"(c[0]), "+f"(c[1]), "+f"(c[2]), "+f"(c[3])
        : "r"(a0), "r"(a1), "r"(a2), "r"(a3), "r"(b0), "r"(b1));
}

__device__ __forceinline__ uint32_t smaddr(const void* p) {
    return (uint32_t)__cvta_generic_to_shared(p);
}
__device__ __forceinline__ void cpa16(uint32_t dst, const void* src) {
    asm volatile("cp.async.cg.shared.global [%0], [%1], 16;" :: "r"(dst), "l"(src));
}
__device__ __forceinline__ void cpa_commit() {
    asm volatile("cp.async.commit_group;" ::: "memory");
}
__device__ __forceinline__ void cpa_wait1() {
    asm volatile("cp.async.wait_group 1;" ::: "memory");
}

// ---------------------------------------------------------------------------
// Pre-round a buffer to tf32 (float4)
// ---------------------------------------------------------------------------
__global__ void round_k(const float* __restrict__ in, float* __restrict__ out, int n4)
{
    int i = blockIdx.x * blockDim.x + threadIdx.x;
    if (i < n4) {
        float4 v = ((const float4*)in)[i];
        ((float4*)out)[i] = make_float4(f2tf_f(v.x), f2tf_f(v.y), f2tf_f(v.z), f2tf_f(v.w));
    }
}

// ---------------------------------------------------------------------------
// GEMM: C = A[M,768] @ W[768,768] + bias. Inputs pre-rounded tf32.
// BM=128, BN=128, BK=32. 256 thr / 8 warps (4m x 2n), warp tile 32x64.
// cp.async 2-stage. Smem: As[2][128][36] + Bs[2][32][136] = 71680 B.
// ---------------------------------------------------------------------------
#define G_AS (128*36)
#define G_BS (32*136)
#define G_SMEM_BYTES ((2*G_AS + 2*G_BS)*4)

template<bool GELU, bool HEADM>
__global__ __launch_bounds__(256, 2) void gemm3(
    const float* __restrict__ A, const float* __restrict__ W,
    const float* __restrict__ bias, float* __restrict__ C)
{
    extern __shared__ float sg[];
    float* Asm = sg;                 // [2][128][36]
    float* Bsm = sg + 2 * G_AS;      // [2][32][136]

    const int tid  = threadIdx.x;
    const int lane = tid & 31;
    const int warp = tid >> 5;
    const int wm   = (warp >> 1) * 32;
    const int wn   = (warp & 1) * 64;
    const int m0   = blockIdx.y * 128;
    const int n0   = blockIdx.x * 128;
    const int c_   = lane & 3;
    const int q_   = lane >> 2;

    const int ar = tid >> 3, ac = (tid & 7) * 4;
    const int br = tid >> 5, bc = (tid & 31) * 4;

    float acc[2][8][4] = {};
    const int nT = HID / 32;   // 24

    // prologue: tile 0 -> buf 0
    {
        #pragma unroll
        for (int i = 0; i < 4; i++) {
            int row = ar + i * 32;
            cpa16(smaddr(&Asm[row * 36 + ac]), &A[(size_t)(m0 + row) * HID + ac]);
        }
        #pragma unroll
        for (int i = 0; i < 4; i++) {
            int row = br + i * 8;
            cpa16(smaddr(&Bsm[row * 136 + bc]), &W[(size_t)row * HID + n0 + bc]);
        }
        cpa_commit();
    }

    for (int t = 0; t < nT; t++) {
        const int cur = t & 1;
        if (t + 1 < nT) {
            const int k0 = (t + 1) * 32;
            float* Ad = Asm + (cur ^ 1) * G_AS;
            float* Bd = Bsm + (cur ^ 1) * G_BS;
            #pragma unroll
            for (int i = 0; i < 4; i++) {
                int row = ar + i * 32;
                cpa16(smaddr(&Ad[row * 36 + ac]), &A[(size_t)(m0 + row) * HID + k0 + ac]);
            }
            #pragma unroll
            for (int i = 0; i < 4; i++) {
                int row = br + i * 8;
                cpa16(smaddr(&Bd[row * 136 + bc]), &W[(size_t)(k0 + row) * HID + n0 + bc]);
            }
        }
        cpa_commit();
        cpa_wait1();
        __syncthreads();

        const float* Ac = Asm + cur * G_AS;
        const float* Bc = Bsm + cur * G_BS;
        #pragma unroll
        for (int ksi = 0; ksi < 4; ksi++) {
            uint32_t a[2][4];
            #pragma unroll
            for (int mt = 0; mt < 2; mt++) {
                int r = wm + mt * 16 + q_;
                a[mt][0] = __float_as_uint(Ac[r * 36 + ksi * 8 + c_]);
                a[mt][1] = __float_as_uint(Ac[(r + 8) * 36 + ksi * 8 + c_]);
                a[mt][2] = __float_as_uint(Ac[r * 36 + ksi * 8 + c_ + 4]);
                a[mt][3] = __float_as_uint(Ac[(r + 8) * 36 + ksi * 8 + c_ + 4]);
            }
            #pragma unroll
            for (int nt = 0; nt < 8; nt++) {
                uint32_t b0 = __float_as_uint(Bc[(ksi * 8 + c_) * 136 + wn + nt * 8 + q_]);
                uint32_t b1 = __float_as_uint(Bc[(ksi * 8 + c_ + 4) * 136 + wn + nt * 8 + q_]);
                mma_tf32(acc[0][nt], a[0][0], a[0][1], a[0][2], a[0][3], b0, b1);
                mma_tf32(acc[1][nt], a[1][0], a[1][1], a[1][2], a[1][3], b0, b1);
            }
        }
        __syncthreads();
    }

    // epilogue
    #pragma unroll
    for (int mt = 0; mt < 2; mt++) {
        int r0 = m0 + wm + mt * 16 + q_;
        #pragma unroll
        for (int nt = 0; nt < 8; nt++) {
            int col = n0 + wn + nt * 8 + 2 * c_;
            float bv0 = bias[col], bv1 = bias[col + 1];
            float v0 = acc[mt][nt][0] + bv0;
            float v1 = acc[mt][nt][1] + bv1;
            float v2 = acc[mt][nt][2] + bv0;
            float v3 = acc[mt][nt][3] + bv1;
            if (GELU) {
                v0 *= normcdff(v0); v1 *= normcdff(v1);
                v2 *= normcdff(v2); v3 *= normcdff(v3);
                *(float2*)&C[(size_t)r0       * HID + col] = make_float2(v0, v1);
                *(float2*)&C[(size_t)(r0 + 8) * HID + col] = make_float2(v2, v3);
            } else if (HEADM) {
                int h = col >> 6, d = col & 63;
                int b0r = r0 >> 11, s0 = r0 & 2047;
                size_t dst0 = ((size_t)(b0r * NH + h) * SEQ + s0) * 64 + d;
                size_t dst1 = dst0 + 8 * 64;
                *(float2*)&C[dst0] = make_float2(f2tf_f(v0), f2tf_f(v1));
                *(float2*)&C[dst1] = make_float2(f2tf_f(v2), f2tf_f(v3));
            } else {
                *(float2*)&C[(size_t)r0       * HID + col] = make_float2(f2tf_f(v0), f2tf_f(v1));
                *(float2*)&C[(size_t)(r0 + 8) * HID + col] = make_float2(f2tf_f(v2), f2tf_f(v3));
            }
        }
    }
}

// ---------------------------------------------------------------------------
// Flash attention, unnormalized streaming softmax (no running max: scores are
// O(10), exp can't overflow fp32; masked -1e9 underflows to exactly 0 — result
// identical to max-subtracted softmax after the final division).
// Block = (b, h, 64-q-tile), 128 thr / 4 warps, 3 CTA/SM.
// Smem: K[2][64][68] + V[2][64][72] + ms[2][64] = 72192 B. P aliases spent K.
// ---------------------------------------------------------------------------
#define A_KS (64*68)
#define A_VS (64*72)
#define A_SMEM_BYTES ((2*A_KS + 2*A_VS + 128)*4)

__global__ __launch_bounds__(128, 3) void attn3(
    const float* __restrict__ qh, const float* __restrict__ kh,
    const float* __restrict__ vh, const float* __restrict__ mask,
    float* __restrict__ ctx)
{
    extern __shared__ float sa[];
    float* Kbuf = sa;                    // [2][64][68]
    float* Vbuf = sa + 2 * A_KS;         // [2][64][72]
    float* msb  = sa + 2 * A_KS + 2 * A_VS;  // [2][64]

    const int tid  = threadIdx.x;
    const int lane = tid & 31;
    const int warp = tid >> 5;
    const int c_   = lane & 3;
    const int q_   = lane >> 2;
    const int b    = blockIdx.z;
    const int h    = blockIdx.y;
    const int q0   = blockIdx.x * 64;
    const int bS   = b * SEQ;
    const int bh   = b * NH + h;
    const float scale = 0.125f;   // 1/sqrt(64)

    const int prow = tid >> 4;
    const int pch  = (tid & 15) * 4;

    const float* kbase0 = &kh[(size_t)bh * SEQ * 64];
    const float* vbase0 = &vh[(size_t)bh * SEQ * 64];

    // prologue: tile 0 -> buf 0
    {
        #pragma unroll
        for (int i = 0; i < 8; i++) {
            int row = prow + i * 8;
            cpa16(smaddr(&Kbuf[row * 68 + pch]), kbase0 + (size_t)row * 64 + pch);
            cpa16(smaddr(&Vbuf[row * 72 + pch]), vbase0 + (size_t)row * 64 + pch);
        }
        if (tid < 16) cpa16(smaddr(&msb[tid * 4]), &mask[bS + tid * 4]);
        cpa_commit();
    }

    // Q fragments in registers for the whole loop
    const int rw = warp * 16 + q_;
    uint32_t qa[8][4];
    {
        const float* p0 = &qh[((size_t)bh * SEQ + q0 + rw) * 64];
        const float* p1 = p0 + 8 * 64;
        #pragma unroll
        for (int ksi = 0; ksi < 8; ksi++) {
            qa[ksi][0] = __float_as_uint(p0[ksi * 8 + c_]);
            qa[ksi][1] = __float_as_uint(p1[ksi * 8 + c_]);
            qa[ksi][2] = __float_as_uint(p0[ksi * 8 + c_ + 4]);
            qa[ksi][3] = __float_as_uint(p1[ksi * 8 + c_ + 4]);
        }
    }
    const float mq0 = mask[bS + q0 + rw];
    const float mq1 = mask[bS + q0 + rw + 8];

    float l0 = 0.0f, l1 = 0.0f;
    float o[8][4] = {};

    const int nT = SEQ / 64;   // 32
    for (int t = 0; t < nT; t++) {
        const int cur = t & 1;
        if (t + 1 < nT) {
            const int k0 = (t + 1) * 64;
            float* Kd = Kbuf + (cur ^ 1) * A_KS;
            float* Vd = Vbuf + (cur ^ 1) * A_VS;
            const float* kb = kbase0 + (size_t)k0 * 64;
            const float* vb = vbase0 + (size_t)k0 * 64;
            #pragma unroll
            for (int i = 0; i < 8; i++) {
                int row = prow + i * 8;
                cpa16(smaddr(&Kd[row * 68 + pch]), kb + (size_t)row * 64 + pch);
                cpa16(smaddr(&Vd[row * 72 + pch]), vb + (size_t)row * 64 + pch);
            }
            if (tid < 16) cpa16(smaddr(&msb[(cur ^ 1) * 64 + tid * 4]), &mask[bS + k0 + tid * 4]);
        }
        cpa_commit();
        cpa_wait1();
        __syncthreads();

        float* Kc = Kbuf + cur * A_KS;
        float* Vc = Vbuf + cur * A_VS;
        const float* mc = msb + cur * 64;

        // ---- S = Q K^T (warp: 16x64)
        float s[8][4] = {};
        #pragma unroll
        for (int ksi = 0; ksi < 8; ksi++) {
            #pragma unroll
            for (int nt = 0; nt < 8; nt++) {
                uint32_t b0 = __float_as_uint(Kc[(nt * 8 + q_) * 68 + ksi * 8 + c_]);
                uint32_t b1 = __float_as_uint(Kc[(nt * 8 + q_) * 68 + ksi * 8 + c_ + 4]);
                mma_tf32(s[nt], qa[ksi][0], qa[ksi][1], qa[ksi][2], qa[ksi][3], b0, b1);
            }
        }

        // ---- mask + exp (no max subtraction), accumulate row sums
        #pragma unroll
        for (int nt = 0; nt < 8; nt++) {
            float mk0 = mc[nt * 8 + 2 * c_];
            float mk1 = mc[nt * 8 + 2 * c_ + 1];
            float e;
            e = mq0 * mk0; s[nt][0] = __expf(e * (s[nt][0] * scale) - (1.0f - e) * 1e9f);
            e = mq0 * mk1; s[nt][1] = __expf(e * (s[nt][1] * scale) - (1.0f - e) * 1e9f);
            e = mq1 * mk0; s[nt][2] = __expf(e * (s[nt][2] * scale) - (1.0f - e) * 1e9f);
            e = mq1 * mk1; s[nt][3] = __expf(e * (s[nt][3] * scale) - (1.0f - e) * 1e9f);
            l0 += s[nt][0] + s[nt][1];
            l1 += s[nt][2] + s[nt][3];
        }

        __syncthreads();   // all warps done reading Kc -> safe to overwrite with P

        // ---- P -> Kc (tf32 bits), rows warp-private
        #pragma unroll
        for (int nt = 0; nt < 8; nt++) {
            *(uint2*)&Kc[rw * 68 + nt * 8 + 2 * c_] =
                make_uint2(f2tf(s[nt][0]), f2tf(s[nt][1]));
            *(uint2*)&Kc[(rw + 8) * 68 + nt * 8 + 2 * c_] =
                make_uint2(f2tf(s[nt][2]), f2tf(s[nt][3]));
        }
        __syncwarp();

        // ---- O += P V (warp: 16x64)
        #pragma unroll
        for (int ksi = 0; ksi < 8; ksi++) {
            uint32_t a0 = __float_as_uint(Kc[rw * 68 + ksi * 8 + c_]);
            uint32_t a1 = __float_as_uint(Kc[(rw + 8) * 68 + ksi * 8 + c_]);
            uint32_t a2 = __float_as_uint(Kc[rw * 68 + ksi * 8 + c_ + 4]);
            uint32_t a3 = __float_as_uint(Kc[(rw + 8) * 68 + ksi * 8 + c_ + 4]);
            #pragma unroll
            for (int nt = 0; nt < 8; nt++) {
                uint32_t b0 = __float_as_uint(Vc[(ksi * 8 + c_) * 72 + nt * 8 + q_]);
                uint32_t b1 = __float_as_uint(Vc[(ksi * 8 + c_ + 4) * 72 + nt * 8 + q_]);
                mma_tf32(o[nt], a0, a1, a2, a3, b0, b1);
            }
        }
        __syncthreads();   // done with Kc (P) / Vc before next producer overwrite
    }

    // ---- final row-sum reduction over the 4-lane group, then normalize
    l0 += __shfl_xor_sync(0xffffffffu, l0, 1);
    l0 += __shfl_xor_sync(0xffffffffu, l0, 2);
    l1 += __shfl_xor_sync(0xffffffffu, l1, 1);
    l1 += __shfl_xor_sync(0xffffffffu, l1, 2);
    float inv0 = 1.0f / l0, inv1 = 1.0f / l1;

    int gr = bS + q0 + rw;
    #pragma unroll
    for (int nt = 0; nt < 8; nt++) {
        int col = h * DH + nt * 8 + 2 * c_;
        *(float2*)&ctx[(size_t)gr * HID + col] =
            make_float2(f2tf_f(o[nt][0] * inv0), f2tf_f(o[nt][1] * inv0));
        *(float2*)&ctx[(size_t)(gr + 8) * HID + col] =
            make_float2(f2tf_f(o[nt][2] * inv1), f2tf_f(o[nt][3] * inv1));
    }
}

// ---------------------------------------------------------------------------
extern "C" void kernel_launch(void* const* d_in, const int* in_sizes, int n_in,
                              void* d_out, int out_size)
{
    const float* hs   = (const float*)d_in[0];
    const float* mask = (const float*)d_in[1];
    const float* Wq   = (const float*)d_in[2];
    const float* bq   = (const float*)d_in[3];
    const float* Wk   = (const float*)d_in[4];
    const float* bk   = (const float*)d_in[5];
    const float* Wv   = (const float*)d_in[6];
    const float* bv   = (const float*)d_in[7];
    const float* Wo   = (const float*)d_in[8];
    const float* bo   = (const float*)d_in[9];
    float* out = (float*)d_out;

    float *hsr, *wr, *qh, *kh, *vh, *cb;
    cudaGetSymbolAddress((void**)&hsr, g_hsr);
    cudaGetSymbolAddress((void**)&wr,  g_wr);
    cudaGetSymbolAddress((void**)&qh,  g_qh);
    cudaGetSymbolAddress((void**)&kh,  g_kh);
    cudaGetSymbolAddress((void**)&vh,  g_vh);
    cudaGetSymbolAddress((void**)&cb,  g_ctx);

    cudaFuncSetAttribute(gemm3<false,true>, cudaFuncAttributeMaxDynamicSharedMemorySize, G_SMEM_BYTES);
    cudaFuncSetAttribute(gemm3<true,false>, cudaFuncAttributeMaxDynamicSharedMemorySize, G_SMEM_BYTES);
    cudaFuncSetAttribute(attn3, cudaFuncAttributeMaxDynamicSharedMemorySize, A_SMEM_BYTES);

    // --- pre-round inputs to tf32 ---
    const int WN4 = HID * HID / 4;
    round_k<<<(MTOT * HID / 4 + 255) / 256, 256>>>(hs, hsr, MTOT * HID / 4);
    round_k<<<(WN4 + 255) / 256, 256>>>(Wq, wr + 0 * HID * HID, WN4);
    round_k<<<(WN4 + 255) / 256, 256>>>(Wk, wr + 1 * HID * HID, WN4);
    round_k<<<(WN4 + 255) / 256, 256>>>(Wv, wr + 2 * HID * HID, WN4);
    round_k<<<(WN4 + 255) / 256, 256>>>(Wo, wr + 3 * HID * HID, WN4);

    // --- projections (write head-major rounded) ---
    dim3 ggrid(HID / 128, MTOT / 128);   // (6, 64)
    gemm3<false,true><<<ggrid, 256, G_SMEM_BYTES>>>(hsr, wr + 0 * HID * HID, bq, qh);
    gemm3<false,true><<<ggrid, 256, G_SMEM_BYTES>>>(hsr, wr + 1 * HID * HID, bk, kh);
    gemm3<false,true><<<ggrid, 256, G_SMEM_BYTES>>>(hsr, wr + 2 * HID * HID, bv, vh);

    // --- attention ---
    dim3 agrid(SEQ / 64, NH, BATCH);     // (32, 12, 4)
    attn3<<<agrid, 128, A_SMEM_BYTES>>>(qh, kh, vh, mask, cb);

    // --- output projection + GELU ---
    gemm3<true,false><<<ggrid, 256, G_SMEM_BYTES>>>(cb, wr + 3 * HID * HID, bo, out);
}

// round 6
// speedup vs baseline: 1.3919x; 1.0122x over previous
#include <cuda_runtime.h>
#include <math.h>
#include <stdint.h>

#define HID   768
#define NH    12
#define DH    64
#define BATCH 4
#define SEQ   2048
#define MTOT  (BATCH*SEQ)   // 8192

// Scratch (allocation-free rule: __device__ globals)
__device__ float g_hsr[MTOT*HID];        // hs rounded to tf32
__device__ float g_wr[4][HID*HID];       // Wq,Wk,Wv,Wo rounded
__device__ float g_qh[MTOT*HID];         // q head-major rounded
__device__ float g_kh[MTOT*HID];
__device__ float g_vh[MTOT*HID];
__device__ float g_ctx[MTOT*HID];        // ctx standard layout, rounded

// ---------------------------------------------------------------------------
__device__ __forceinline__ uint32_t f2tf(float x) {
    uint32_t r;
    asm("cvt.rna.tf32.f32 %0, %1;" : "=r"(r) : "f"(x));
    return r;
}
__device__ __forceinline__ float f2tf_f(float x) {
    uint32_t u = f2tf(x); return __uint_as_float(u);
}

__device__ __forceinline__ void mma_tf32(float c[4],
    uint32_t a0, uint32_t a1, uint32_t a2, uint32_t a3,
    uint32_t b0, uint32_t b1)
{
    asm volatile(
        "mma.sync.aligned.m16n8k8.row.col.f32.tf32.tf32.f32 "
        "{%0,%1,%2,%3}, {%4,%5,%6,%7}, {%8,%9}, {%0,%1,%2,%3};"
        : "+f"(c[0]), "+f"(c[1]), "+f"(c[2]), "+f"(c[3])
        : "r"(a0), "r"(a1), "r"(a2), "r"(a3), "r"(b0), "r"(b1));
}

__device__ __forceinline__ uint32_t smaddr(const void* p) {
    return (uint32_t)__cvta_generic_to_shared(p);
}
__device__ __forceinline__ void cpa16(uint32_t dst, const void* src) {
    asm volatile("cp.async.cg.shared.global [%0], [%1], 16;" :: "r"(dst), "l"(src));
}
__device__ __forceinline__ void cpa_commit() {
    asm volatile("cp.async.commit_group;" ::: "memory");
}
__device__ __forceinline__ void cpa_wait1() {
    asm volatile("cp.async.wait_group 1;" ::: "memory");
}

// ---------------------------------------------------------------------------
// Pre-round kernels
// ---------------------------------------------------------------------------
__global__ void round_hs(const float* __restrict__ in, float* __restrict__ out, int n4)
{
    int i = blockIdx.x * blockDim.x + threadIdx.x;
    if (i < n4) {
        float4 v = ((const float4*)in)[i];
        ((float4*)out)[i] = make_float4(f2tf_f(v.x), f2tf_f(v.y), f2tf_f(v.z), f2tf_f(v.w));
    }
}
__global__ void round_w4(const float* __restrict__ w0, const float* __restrict__ w1,
                         const float* __restrict__ w2, const float* __restrict__ w3,
                         float* __restrict__ out)
{
    const int wi = blockIdx.y;
    const float* src = wi == 0 ? w0 : (wi == 1 ? w1 : (wi == 2 ? w2 : w3));
    float* dst = out + (size_t)wi * HID * HID;
    int i = blockIdx.x * blockDim.x + threadIdx.x;
    if (i < HID * HID / 4) {
        float4 v = ((const float4*)src)[i];
        ((float4*)dst)[i] = make_float4(f2tf_f(v.x), f2tf_f(v.y), f2tf_f(v.z), f2tf_f(v.w));
    }
}

// ---------------------------------------------------------------------------
// GEMM body: C = A[M,768] @ W[768,768] + bias. Inputs pre-rounded tf32.
// BM=128, BN=128, BK=32. 128 thr / 4 warps (2m x 2n), warp tile 64x64.
// cp.async 2-stage. Smem: As[2][128][36] + Bs[2][32][136] = 71680 B, 2 CTA/SM.
// ---------------------------------------------------------------------------
#define G_AS (128*36)
#define G_BS (32*136)
#define G_SMEM_BYTES ((2*G_AS + 2*G_BS)*4)

template<bool GELU, bool HEADM>
__device__ __forceinline__ void gemm_body(
    const float* __restrict__ A, const float* __restrict__ W,
    const float* __restrict__ bias, float* __restrict__ C)
{
    extern __shared__ float sg[];
    float* Asm = sg;                 // [2][128][36]
    float* Bsm = sg + 2 * G_AS;      // [2][32][136]

    const int tid  = threadIdx.x;
    const int lane = tid & 31;
    const int warp = tid >> 5;
    const int wm   = (warp >> 1) * 64;
    const int wn   = (warp & 1) * 64;
    const int m0   = blockIdx.y * 128;
    const int n0   = blockIdx.x * 128;
    const int c_   = lane & 3;
    const int q_   = lane >> 2;

    const int ar = tid >> 3, ac = (tid & 7) * 4;   // A producer: 8 rows apart by 16
    const int br = tid >> 5, bc = (tid & 31) * 4;  // B producer: 8 rows apart by 4

    float acc[4][8][4] = {};
    const int nT = HID / 32;   // 24

    // prologue: tile 0 -> buf 0
    {
        #pragma unroll
        for (int i = 0; i < 8; i++) {
            int row = ar + i * 16;
            cpa16(smaddr(&Asm[row * 36 + ac]), &A[(size_t)(m0 + row) * HID + ac]);
        }
        #pragma unroll
        for (int i = 0; i < 8; i++) {
            int row = br + i * 4;
            cpa16(smaddr(&Bsm[row * 136 + bc]), &W[(size_t)row * HID + n0 + bc]);
        }
        cpa_commit();
    }

    for (int t = 0; t < nT; t++) {
        const int cur = t & 1;
        if (t + 1 < nT) {
            const int k0 = (t + 1) * 32;
            float* Ad = Asm + (cur ^ 1) * G_AS;
            float* Bd = Bsm + (cur ^ 1) * G_BS;
            #pragma unroll
            for (int i = 0; i < 8; i++) {
                int row = ar + i * 16;
                cpa16(smaddr(&Ad[row * 36 + ac]), &A[(size_t)(m0 + row) * HID + k0 + ac]);
            }
            #pragma unroll
            for (int i = 0; i < 8; i++) {
                int row = br + i * 4;
                cpa16(smaddr(&Bd[row * 136 + bc]), &W[(size_t)(k0 + row) * HID + n0 + bc]);
            }
        }
        cpa_commit();
        cpa_wait1();
        __syncthreads();

        const float* Ac = Asm + cur * G_AS;
        const float* Bc = Bsm + cur * G_BS;
        #pragma unroll
        for (int ksi = 0; ksi < 4; ksi++) {
            uint32_t a[4][4];
            #pragma unroll
            for (int mt = 0; mt < 4; mt++) {
                int r = wm + mt * 16 + q_;
                a[mt][0] = __float_as_uint(Ac[r * 36 + ksi * 8 + c_]);
                a[mt][1] = __float_as_uint(Ac[(r + 8) * 36 + ksi * 8 + c_]);
                a[mt][2] = __float_as_uint(Ac[r * 36 + ksi * 8 + c_ + 4]);
                a[mt][3] = __float_as_uint(Ac[(r + 8) * 36 + ksi * 8 + c_ + 4]);
            }
            #pragma unroll
            for (int nt = 0; nt < 8; nt++) {
                uint32_t b0 = __float_as_uint(Bc[(ksi * 8 + c_) * 136 + wn + nt * 8 + q_]);
                uint32_t b1 = __float_as_uint(Bc[(ksi * 8 + c_ + 4) * 136 + wn + nt * 8 + q_]);
                #pragma unroll
                for (int mt = 0; mt < 4; mt++)
                    mma_tf32(acc[mt][nt], a[mt][0], a[mt][1], a[mt][2], a[mt][3], b0, b1);
            }
        }
        __syncthreads();   // protect cur buffer before it is refilled next+1 iter
    }

    // epilogue
    #pragma unroll
    for (int mt = 0; mt < 4; mt++) {
        int r0 = m0 + wm + mt * 16 + q_;
        #pragma unroll
        for (int nt = 0; nt < 8; nt++) {
            int col = n0 + wn + nt * 8 + 2 * c_;
            float bv0 = bias[col], bv1 = bias[col + 1];
            float v0 = acc[mt][nt][0] + bv0;
            float v1 = acc[mt][nt][1] + bv1;
            float v2 = acc[mt][nt][2] + bv0;
            float v3 = acc[mt][nt][3] + bv1;
            if (GELU) {
                v0 *= normcdff(v0); v1 *= normcdff(v1);
                v2 *= normcdff(v2); v3 *= normcdff(v3);
                *(float2*)&C[(size_t)r0       * HID + col] = make_float2(v0, v1);
                *(float2*)&C[(size_t)(r0 + 8) * HID + col] = make_float2(v2, v3);
            } else if (HEADM) {
                int h = col >> 6, d = col & 63;
                int b0r = r0 >> 11, s0 = r0 & 2047;
                size_t dst0 = ((size_t)(b0r * NH + h) * SEQ + s0) * 64 + d;
                size_t dst1 = dst0 + 8 * 64;
                *(float2*)&C[dst0] = make_float2(f2tf_f(v0), f2tf_f(v1));
                *(float2*)&C[dst1] = make_float2(f2tf_f(v2), f2tf_f(v3));
            } else {
                *(float2*)&C[(size_t)r0       * HID + col] = make_float2(f2tf_f(v0), f2tf_f(v1));
                *(float2*)&C[(size_t)(r0 + 8) * HID + col] = make_float2(f2tf_f(v2), f2tf_f(v3));
            }
        }
    }
}

template<bool GELU, bool HEADM>
__global__ __launch_bounds__(128, 2) void gemm4(
    const float* __restrict__ A, const float* __restrict__ W,
    const float* __restrict__ bias, float* __restrict__ C)
{
    gemm_body<GELU, HEADM>(A, W, bias, C);
}

// Fused QKV: blockIdx.z selects weight/bias/output
__global__ __launch_bounds__(128, 2) void gemm4_qkv(
    const float* __restrict__ A,
    const float* __restrict__ W0, const float* __restrict__ W1, const float* __restrict__ W2,
    const float* __restrict__ b0, const float* __restrict__ b1, const float* __restrict__ b2,
    float* __restrict__ C0, float* __restrict__ C1, float* __restrict__ C2)
{
    const int z = blockIdx.z;
    const float* W = z == 0 ? W0 : (z == 1 ? W1 : W2);
    const float* bb = z == 0 ? b0 : (z == 1 ? b1 : b2);
    float* C = z == 0 ? C0 : (z == 1 ? C1 : C2);
    gemm_body<false, true>(A, W, bb, C);
}

// ---------------------------------------------------------------------------
// Flash attention, unnormalized streaming softmax (scores O(10): exp can't
// overflow fp32; masked -1e9 underflows to exactly 0).
// Block = (b, h, 256-q-tile), 256 thr / 8 warps, warp = 32 q-rows (2 m-tiles).
// Smem: Qs[256][68] + Ps[256][72] + K[2][64][68] + V[2][64][72] + ms[2][64]
//     = 69632 + 73728 + 34816 + 36864 + 512 = 215552 B -> 1 CTA/SM.
// ---------------------------------------------------------------------------
#define A_KS (64*68)
#define A_VS (64*72)
#define A_Q_OFF 0
#define A_P_OFF (256*68)
#define A_K_OFF (A_P_OFF + 256*72)
#define A_V_OFF (A_K_OFF + 2*A_KS)
#define A_M_OFF (A_V_OFF + 2*A_VS)
#define A_SMEM_BYTES ((A_M_OFF + 128)*4)

__global__ __launch_bounds__(256, 1) void attn4(
    const float* __restrict__ qh, const float* __restrict__ kh,
    const float* __restrict__ vh, const float* __restrict__ mask,
    float* __restrict__ ctx)
{
    extern __shared__ float sa[];
    float* Qs   = sa + A_Q_OFF;   // [256][68]
    float* Ps   = sa + A_P_OFF;   // [256][72]
    float* Kbuf = sa + A_K_OFF;   // [2][64][68]
    float* Vbuf = sa + A_V_OFF;   // [2][64][72]
    float* msb  = sa + A_M_OFF;   // [2][64]

    const int tid  = threadIdx.x;
    const int lane = tid & 31;
    const int warp = tid >> 5;
    const int c_   = lane & 3;
    const int q_   = lane >> 2;
    const int b    = blockIdx.z;
    const int h    = blockIdx.y;
    const int q0   = blockIdx.x * 256;
    const int bS   = b * SEQ;
    const int bh   = b * NH + h;
    const int wq   = warp * 32;
    const float scale = 0.125f;   // 1/sqrt(64)

    const int prow = tid >> 4;          // 0..15
    const int pch  = (tid & 15) * 4;

    const float* kbase0 = &kh[(size_t)bh * SEQ * 64];
    const float* vbase0 = &vh[(size_t)bh * SEQ * 64];
    const float* qbase  = &qh[((size_t)bh * SEQ + q0) * 64];

    // prologue group: Q tile (256x64), K/V tile 0, mask 0
    {
        #pragma unroll
        for (int i = 0; i < 16; i++) {
            int idx = tid + i * 256;          // 4096 float4
            int row = idx >> 4, col = (idx & 15) * 4;
            cpa16(smaddr(&Qs[row * 68 + col]), qbase + (size_t)row * 64 + col);
        }
        #pragma unroll
        for (int i = 0; i < 4; i++) {
            int row = prow + i * 16;
            cpa16(smaddr(&Kbuf[row * 68 + pch]), kbase0 + (size_t)row * 64 + pch);
            cpa16(smaddr(&Vbuf[row * 72 + pch]), vbase0 + (size_t)row * 64 + pch);
        }
        if (tid < 16) cpa16(smaddr(&msb[tid * 4]), &mask[bS + tid * 4]);
        cpa_commit();
    }

    // per-thread row masks
    float mq[2][2];
    #pragma unroll
    for (int mt = 0; mt < 2; mt++) {
        mq[mt][0] = mask[bS + q0 + wq + mt * 16 + q_];
        mq[mt][1] = mask[bS + q0 + wq + mt * 16 + q_ + 8];
    }

    float l[2][2] = {};
    float o[2][8][4] = {};

    const int nT = SEQ / 64;   // 32
    for (int t = 0; t < nT; t++) {
        const int cur = t & 1;
        if (t + 1 < nT) {
            const int k0 = (t + 1) * 64;
            float* Kd = Kbuf + (cur ^ 1) * A_KS;
            float* Vd = Vbuf + (cur ^ 1) * A_VS;
            const float* kb = kbase0 + (size_t)k0 * 64;
            const float* vb = vbase0 + (size_t)k0 * 64;
            #pragma unroll
            for (int i = 0; i < 4; i++) {
                int row = prow + i * 16;
                cpa16(smaddr(&Kd[row * 68 + pch]), kb + (size_t)row * 64 + pch);
                cpa16(smaddr(&Vd[row * 72 + pch]), vb + (size_t)row * 64 + pch);
            }
            if (tid < 16) cpa16(smaddr(&msb[(cur ^ 1) * 64 + tid * 4]), &mask[bS + k0 + tid * 4]);
        }
        cpa_commit();
        cpa_wait1();
        __syncthreads();

        float* Kc = Kbuf + cur * A_KS;
        float* Vc = Vbuf + cur * A_VS;
        const float* mc = msb + cur * 64;

        // ---- S = Q K^T (warp: 32x64)
        float s[2][8][4] = {};
        #pragma unroll
        for (int ksi = 0; ksi < 8; ksi++) {
            uint32_t a[2][4];
            #pragma unroll
            for (int mt = 0; mt < 2; mt++) {
                int r = wq + mt * 16 + q_;
                a[mt][0] = __float_as_uint(Qs[r * 68 + ksi * 8 + c_]);
                a[mt][1] = __float_as_uint(Qs[(r + 8) * 68 + ksi * 8 + c_]);
                a[mt][2] = __float_as_uint(Qs[r * 68 + ksi * 8 + c_ + 4]);
                a[mt][3] = __float_as_uint(Qs[(r + 8) * 68 + ksi * 8 + c_ + 4]);
            }
            #pragma unroll
            for (int nt = 0; nt < 8; nt++) {
                uint32_t b0 = __float_as_uint(Kc[(nt * 8 + q_) * 68 + ksi * 8 + c_]);
                uint32_t b1 = __float_as_uint(Kc[(nt * 8 + q_) * 68 + ksi * 8 + c_ + 4]);
                mma_tf32(s[0][nt], a[0][0], a[0][1], a[0][2], a[0][3], b0, b1);
                mma_tf32(s[1][nt], a[1][0], a[1][1], a[1][2], a[1][3], b0, b1);
            }
        }

        // ---- mask + exp (no max subtraction), accumulate row sums
        #pragma unroll
        for (int mt = 0; mt < 2; mt++) {
            #pragma unroll
            for (int nt = 0; nt < 8; nt++) {
                float mk0 = mc[nt * 8 + 2 * c_];
                float mk1 = mc[nt * 8 + 2 * c_ + 1];
                float e;
                e = mq[mt][0] * mk0; s[mt][nt][0] = __expf(e * (s[mt][nt][0] * scale) - (1.0f - e) * 1e9f);
                e = mq[mt][0] * mk1; s[mt][nt][1] = __expf(e * (s[mt][nt][1] * scale) - (1.0f - e) * 1e9f);
                e = mq[mt][1] * mk0; s[mt][nt][2] = __expf(e * (s[mt][nt][2] * scale) - (1.0f - e) * 1e9f);
                e = mq[mt][1] * mk1; s[mt][nt][3] = __expf(e * (s[mt][nt][3] * scale) - (1.0f - e) * 1e9f);
                l[mt][0] += s[mt][nt][0] + s[mt][nt][1];
                l[mt][1] += s[mt][nt][2] + s[mt][nt][3];
            }
        }

        // ---- P -> Ps (warp-private rows, stride 72 conflict-free)
        #pragma unroll
        for (int mt = 0; mt < 2; mt++) {
            int r = wq + mt * 16 + q_;
            #pragma unroll
            for (int nt = 0; nt < 8; nt++) {
                *(uint2*)&Ps[r * 72 + nt * 8 + 2 * c_] =
                    make_uint2(f2tf(s[mt][nt][0]), f2tf(s[mt][nt][1]));
                *(uint2*)&Ps[(r + 8) * 72 + nt * 8 + 2 * c_] =
                    make_uint2(f2tf(s[mt][nt][2]), f2tf(s[mt][nt][3]));
            }
        }
        __syncwarp();

        // ---- O += P V (warp: 32x64)
        #pragma unroll
        for (int ksi = 0; ksi < 8; ksi++) {
            uint32_t a[2][4];
            #pragma unroll
            for (int mt = 0; mt < 2; mt++) {
                int r = wq + mt * 16 + q_;
                a[mt][0] = __float_as_uint(Ps[r * 72 + ksi * 8 + c_]);
                a[mt][1] = __float_as_uint(Ps[(r + 8) * 72 + ksi * 8 + c_]);
                a[mt][2] = __float_as_uint(Ps[r * 72 + ksi * 8 + c_ + 4]);
                a[mt][3] = __float_as_uint(Ps[(r + 8) * 72 + ksi * 8 + c_ + 4]);
            }
            #pragma unroll
            for (int nt = 0; nt < 8; nt++) {
                uint32_t b0 = __float_as_uint(Vc[(ksi * 8 + c_) * 72 + nt * 8 + q_]);
                uint32_t b1 = __float_as_uint(Vc[(ksi * 8 + c_ + 4) * 72 + nt * 8 + q_]);
                mma_tf32(o[0][nt], a[0][0], a[0][1], a[0][2], a[0][3], b0, b1);
                mma_tf32(o[1][nt], a[1][0], a[1][1], a[1][2], a[1][3], b0, b1);
            }
        }
        __syncthreads();   // protect Kc/Vc/mc before next iteration's prefetch overwrite
    }

    // ---- final row-sum reduction over 4-lane group, normalize, write
    #pragma unroll
    for (int mt = 0; mt < 2; mt++) {
        #pragma unroll
        for (int half = 0; half < 2; half++) {
            l[mt][half] += __shfl_xor_sync(0xffffffffu, l[mt][half], 1);
            l[mt][half] += __shfl_xor_sync(0xffffffffu, l[mt][half], 2);
        }
    }

    #pragma unroll
    for (int mt = 0; mt < 2; mt++) {
        float inv0 = 1.0f / l[mt][0], inv1 = 1.0f / l[mt][1];
        int gr = bS + q0 + wq + mt * 16 + q_;
        #pragma unroll
        for (int nt = 0; nt < 8; nt++) {
            int col = h * DH + nt * 8 + 2 * c_;
            *(float2*)&ctx[(size_t)gr * HID + col] =
                make_float2(f2tf_f(o[mt][nt][0] * inv0), f2tf_f(o[mt][nt][1] * inv0));
            *(float2*)&ctx[(size_t)(gr + 8) * HID + col] =
                make_float2(f2tf_f(o[mt][nt][2] * inv1), f2tf_f(o[mt][nt][3] * inv1));
        }
    }
}

// ---------------------------------------------------------------------------
extern "C" void kernel_launch(void* const* d_in, const int* in_sizes, int n_in,
                              void* d_out, int out_size)
{
    const float* hs   = (const float*)d_in[0];
    const float* mask = (const float*)d_in[1];
    const float* Wq   = (const float*)d_in[2];
    const float* bq   = (const float*)d_in[3];
    const float* Wk   = (const float*)d_in[4];
    const float* bk   = (const float*)d_in[5];
    const float* Wv   = (const float*)d_in[6];
    const float* bv   = (const float*)d_in[7];
    const float* Wo   = (const float*)d_in[8];
    const float* bo   = (const float*)d_in[9];
    float* out = (float*)d_out;

    float *hsr, *wr, *qh, *kh, *vh, *cb;
    cudaGetSymbolAddress((void**)&hsr, g_hsr);
    cudaGetSymbolAddress((void**)&wr,  g_wr);
    cudaGetSymbolAddress((void**)&qh,  g_qh);
    cudaGetSymbolAddress((void**)&kh,  g_kh);
    cudaGetSymbolAddress((void**)&vh,  g_vh);
    cudaGetSymbolAddress((void**)&cb,  g_ctx);

    cudaFuncSetAttribute(gemm4_qkv,         cudaFuncAttributeMaxDynamicSharedMemorySize, G_SMEM_BYTES);
    cudaFuncSetAttribute(gemm4<true,false>, cudaFuncAttributeMaxDynamicSharedMemorySize, G_SMEM_BYTES);
    cudaFuncSetAttribute(attn4,             cudaFuncAttributeMaxDynamicSharedMemorySize, A_SMEM_BYTES);

    // --- pre-round inputs to tf32 ---
    round_hs<<<(MTOT * HID / 4 + 255) / 256, 256>>>(hs, hsr, MTOT * HID / 4);
    dim3 wgrid((HID * HID / 4 + 255) / 256, 4);
    round_w4<<<wgrid, 256>>>(Wq, Wk, Wv, Wo, wr);

    // --- fused QKV projections (write head-major rounded) ---
    dim3 qkvgrid(HID / 128, MTOT / 128, 3);   // (6, 64, 3)
    gemm4_qkv<<<qkvgrid, 128, G_SMEM_BYTES>>>(
        hsr,
        wr + 0 * (size_t)HID * HID, wr + 1 * (size_t)HID * HID, wr + 2 * (size_t)HID * HID,
        bq, bk, bv, qh, kh, vh);

    // --- attention ---
    dim3 agrid(SEQ / 256, NH, BATCH);    // (8, 12, 4)
    attn4<<<agrid, 256, A_SMEM_BYTES>>>(qh, kh, vh, mask, cb);

    // --- output projection + GELU ---
    dim3 ggrid(HID / 128, MTOT / 128);   // (6, 64)
    gemm4<true,false><<<ggrid, 128, G_SMEM_BYTES>>>(cb, wr + 3 * (size_t)HID * HID, bo, out);
}

// round 7
// speedup vs baseline: 1.4679x; 1.0546x over previous
#include <cuda_runtime.h>
#include <math.h>
#include <stdint.h>

#define HID   768
#define NH    12
#define DH    64
#define BATCH 4
#define SEQ   2048
#define MTOT  (BATCH*SEQ)   // 8192

// Scratch (allocation-free rule: __device__ globals)
__device__ float g_hsr[MTOT*HID];        // hs rounded to tf32
__device__ float g_wr[4][HID*HID];       // Wq,Wk,Wv,Wo rounded
__device__ float g_qh[MTOT*HID];         // q head-major rounded
__device__ float g_kh[MTOT*HID];
__device__ float g_vh[MTOT*HID];
__device__ float g_ctx[MTOT*HID];        // ctx standard layout, rounded

// ---------------------------------------------------------------------------
__device__ __forceinline__ uint32_t f2tf(float x) {
    uint32_t r;
    asm("cvt.rna.tf32.f32 %0, %1;" : "=r"(r) : "f"(x));
    return r;
}
__device__ __forceinline__ float f2tf_f(float x) {
    uint32_t u = f2tf(x); return __uint_as_float(u);
}
__device__ __forceinline__ float fexp2(float x) {
    float y;
    asm("ex2.approx.f32 %0, %1;" : "=f"(y) : "f"(x));
    return y;
}

__device__ __forceinline__ void mma_tf32(float c[4],
    uint32_t a0, uint32_t a1, uint32_t a2, uint32_t a3,
    uint32_t b0, uint32_t b1)
{
    asm volatile(
        "mma.sync.aligned.m16n8k8.row.col.f32.tf32.tf32.f32 "
        "{%0,%1,%2,%3}, {%4,%5,%6,%7}, {%8,%9}, {%0,%1,%2,%3};"
        : "+f"(c[0]), "+f"(c[1]), "+f"(c[2]), "+f"(c[3])
        : "r"(a0), "r"(a1), "r"(a2), "r"(a3), "r"(b0), "r"(b1));
}

__device__ __forceinline__ uint32_t smaddr(const void* p) {
    return (uint32_t)__cvta_generic_to_shared(p);
}
__device__ __forceinline__ void cpa16(uint32_t dst, const void* src) {
    asm volatile("cp.async.cg.shared.global [%0], [%1], 16;" :: "r"(dst), "l"(src));
}
__device__ __forceinline__ void cpa_commit() {
    asm volatile("cp.async.commit_group;" ::: "memory");
}
__device__ __forceinline__ void cpa_wait1() {
    asm volatile("cp.async.wait_group 1;" ::: "memory");
}

// ---------------------------------------------------------------------------
// Pre-round kernels
// ---------------------------------------------------------------------------
__global__ void round_hs(const float* __restrict__ in, float* __restrict__ out, int n4)
{
    int i = blockIdx.x * blockDim.x + threadIdx.x;
    if (i < n4) {
        float4 v = ((const float4*)in)[i];
        ((float4*)out)[i] = make_float4(f2tf_f(v.x), f2tf_f(v.y), f2tf_f(v.z), f2tf_f(v.w));
    }
}
__global__ void round_w4(const float* __restrict__ w0, const float* __restrict__ w1,
                         const float* __restrict__ w2, const float* __restrict__ w3,
                         float* __restrict__ out)
{
    const int wi = blockIdx.y;
    const float* src = wi == 0 ? w0 : (wi == 1 ? w1 : (wi == 2 ? w2 : w3));
    float* dst = out + (size_t)wi * HID * HID;
    int i = blockIdx.x * blockDim.x + threadIdx.x;
    if (i < HID * HID / 4) {
        float4 v = ((const float4*)src)[i];
        ((float4*)dst)[i] = make_float4(f2tf_f(v.x), f2tf_f(v.y), f2tf_f(v.z), f2tf_f(v.w));
    }
}

// ---------------------------------------------------------------------------
// GEMM body: C = A[M,768] @ W[768,768] + bias. Inputs pre-rounded tf32.
// BM=128, BN=128, BK=32. 128 thr / 4 warps (2m x 2n), warp tile 64x64.
// cp.async 2-stage. Smem: As[2][128][36] + Bs[2][32][136] = 71680 B, 2 CTA/SM.
// ---------------------------------------------------------------------------
#define G_AS (128*36)
#define G_BS (32*136)
#define G_SMEM_BYTES ((2*G_AS + 2*G_BS)*4)

template<bool GELU, bool HEADM>
__device__ __forceinline__ void gemm_body(
    const float* __restrict__ A, const float* __restrict__ W,
    const float* __restrict__ bias, float* __restrict__ C)
{
    extern __shared__ float sg[];
    float* Asm = sg;                 // [2][128][36]
    float* Bsm = sg + 2 * G_AS;      // [2][32][136]

    const int tid  = threadIdx.x;
    const int lane = tid & 31;
    const int warp = tid >> 5;
    const int wm   = (warp >> 1) * 64;
    const int wn   = (warp & 1) * 64;
    const int m0   = blockIdx.y * 128;
    const int n0   = blockIdx.x * 128;
    const int c_   = lane & 3;
    const int q_   = lane >> 2;

    const int ar = tid >> 3, ac = (tid & 7) * 4;
    const int br = tid >> 5, bc = (tid & 31) * 4;

    float acc[4][8][4] = {};
    const int nT = HID / 32;   // 24

    // prologue: tile 0 -> buf 0
    {
        #pragma unroll
        for (int i = 0; i < 8; i++) {
            int row = ar + i * 16;
            cpa16(smaddr(&Asm[row * 36 + ac]), &A[(size_t)(m0 + row) * HID + ac]);
        }
        #pragma unroll
        for (int i = 0; i < 8; i++) {
            int row = br + i * 4;
            cpa16(smaddr(&Bsm[row * 136 + bc]), &W[(size_t)row * HID + n0 + bc]);
        }
        cpa_commit();
    }

    for (int t = 0; t < nT; t++) {
        const int cur = t & 1;
        if (t + 1 < nT) {
            const int k0 = (t + 1) * 32;
            float* Ad = Asm + (cur ^ 1) * G_AS;
            float* Bd = Bsm + (cur ^ 1) * G_BS;
            #pragma unroll
            for (int i = 0; i < 8; i++) {
                int row = ar + i * 16;
                cpa16(smaddr(&Ad[row * 36 + ac]), &A[(size_t)(m0 + row) * HID + k0 + ac]);
            }
            #pragma unroll
            for (int i = 0; i < 8; i++) {
                int row = br + i * 4;
                cpa16(smaddr(&Bd[row * 136 + bc]), &W[(size_t)(k0 + row) * HID + n0 + bc]);
            }
        }
        cpa_commit();
        cpa_wait1();
        __syncthreads();

        const float* Ac = Asm + cur * G_AS;
        const float* Bc = Bsm + cur * G_BS;
        #pragma unroll
        for (int ksi = 0; ksi < 4; ksi++) {
            uint32_t a[4][4];
            #pragma unroll
            for (int mt = 0; mt < 4; mt++) {
                int r = wm + mt * 16 + q_;
                a[mt][0] = __float_as_uint(Ac[r * 36 + ksi * 8 + c_]);
                a[mt][1] = __float_as_uint(Ac[(r + 8) * 36 + ksi * 8 + c_]);
                a[mt][2] = __float_as_uint(Ac[r * 36 + ksi * 8 + c_ + 4]);
                a[mt][3] = __float_as_uint(Ac[(r + 8) * 36 + ksi * 8 + c_ + 4]);
            }
            #pragma unroll
            for (int nt = 0; nt < 8; nt++) {
                uint32_t b0 = __float_as_uint(Bc[(ksi * 8 + c_) * 136 + wn + nt * 8 + q_]);
                uint32_t b1 = __float_as_uint(Bc[(ksi * 8 + c_ + 4) * 136 + wn + nt * 8 + q_]);
                #pragma unroll
                for (int mt = 0; mt < 4; mt++)
                    mma_tf32(acc[mt][nt], a[mt][0], a[mt][1], a[mt][2], a[mt][3], b0, b1);
            }
        }
        __syncthreads();
    }

    // epilogue
    #pragma unroll
    for (int mt = 0; mt < 4; mt++) {
        int r0 = m0 + wm + mt * 16 + q_;
        #pragma unroll
        for (int nt = 0; nt < 8; nt++) {
            int col = n0 + wn + nt * 8 + 2 * c_;
            float bv0 = bias[col], bv1 = bias[col + 1];
            float v0 = acc[mt][nt][0] + bv0;
            float v1 = acc[mt][nt][1] + bv1;
            float v2 = acc[mt][nt][2] + bv0;
            float v3 = acc[mt][nt][3] + bv1;
            if (GELU) {
                v0 *= normcdff(v0); v1 *= normcdff(v1);
                v2 *= normcdff(v2); v3 *= normcdff(v3);
                *(float2*)&C[(size_t)r0       * HID + col] = make_float2(v0, v1);
                *(float2*)&C[(size_t)(r0 + 8) * HID + col] = make_float2(v2, v3);
            } else if (HEADM) {
                int h = col >> 6, d = col & 63;
                int b0r = r0 >> 11, s0 = r0 & 2047;
                size_t dst0 = ((size_t)(b0r * NH + h) * SEQ + s0) * 64 + d;
                size_t dst1 = dst0 + 8 * 64;
                *(float2*)&C[dst0] = make_float2(f2tf_f(v0), f2tf_f(v1));
                *(float2*)&C[dst1] = make_float2(f2tf_f(v2), f2tf_f(v3));
            } else {
                *(float2*)&C[(size_t)r0       * HID + col] = make_float2(f2tf_f(v0), f2tf_f(v1));
                *(float2*)&C[(size_t)(r0 + 8) * HID + col] = make_float2(f2tf_f(v2), f2tf_f(v3));
            }
        }
    }
}

template<bool GELU, bool HEADM>
__global__ __launch_bounds__(128, 2) void gemm4(
    const float* __restrict__ A, const float* __restrict__ W,
    const float* __restrict__ bias, float* __restrict__ C)
{
    gemm_body<GELU, HEADM>(A, W, bias, C);
}

__global__ __launch_bounds__(128, 2) void gemm4_qkv(
    const float* __restrict__ A,
    const float* __restrict__ W0, const float* __restrict__ W1, const float* __restrict__ W2,
    const float* __restrict__ b0, const float* __restrict__ b1, const float* __restrict__ b2,
    float* __restrict__ C0, float* __restrict__ C1, float* __restrict__ C2)
{
    const int z = blockIdx.z;
    const float* W = z == 0 ? W0 : (z == 1 ? W1 : W2);
    const float* bb = z == 0 ? b0 : (z == 1 ? b1 : b2);
    float* C = z == 0 ? C0 : (z == 1 ? C1 : C2);
    gemm_body<false, true>(A, W, bb, C);
}

// ---------------------------------------------------------------------------
// Flash attention, unnormalized streaming softmax.
// Block = (b, h, 128-q-tile), 128 thr / 4 warps, warp = 32 q-rows (2 m-tiles).
// Q fragments in registers (loaded once). P in dedicated smem (stride 68 ->
// conflict-free A-fragment reads). 2 CTA/SM.
// Smem: Ps[128][68] + K[2][64][68] + V[2][64][72] + ms[2][64]
//     = 34816 + 34816 + 36864 + 512 = 107008 B.
// ---------------------------------------------------------------------------
#define A_KS (64*68)
#define A_VS (64*72)
#define A_P_OFF 0
#define A_K_OFF (128*68)
#define A_V_OFF (A_K_OFF + 2*A_KS)
#define A_M_OFF (A_V_OFF + 2*A_VS)
#define A_SMEM_BYTES ((A_M_OFF + 128)*4)

__global__ __launch_bounds__(128, 2) void attn5(
    const float* __restrict__ qh, const float* __restrict__ kh,
    const float* __restrict__ vh, const float* __restrict__ mask,
    float* __restrict__ ctx)
{
    extern __shared__ float sa[];
    float* Ps   = sa + A_P_OFF;   // [128][68]
    float* Kbuf = sa + A_K_OFF;   // [2][64][68]
    float* Vbuf = sa + A_V_OFF;   // [2][64][72]
    float* msb  = sa + A_M_OFF;   // [2][64]

    const int tid  = threadIdx.x;
    const int lane = tid & 31;
    const int warp = tid >> 5;
    const int c_   = lane & 3;
    const int q_   = lane >> 2;
    const int b    = blockIdx.z;
    const int h    = blockIdx.y;
    const int q0   = blockIdx.x * 128;
    const int bS   = b * SEQ;
    const int bh   = b * NH + h;
    const int wq   = warp * 32;
    // exp2 folding: exp(x) = exp2(x * log2e)
    const float scale2 = 0.125f * 1.44269504f;
    const float pen2   = 1e9f * 1.44269504f;

    const int prow = tid >> 4;          // 0..7
    const int pch  = (tid & 15) * 4;

    const float* kbase0 = &kh[(size_t)bh * SEQ * 64];
    const float* vbase0 = &vh[(size_t)bh * SEQ * 64];

    // prologue: K/V tile 0 + mask 0
    {
        #pragma unroll
        for (int i = 0; i < 8; i++) {
            int row = prow + i * 8;
            cpa16(smaddr(&Kbuf[row * 68 + pch]), kbase0 + (size_t)row * 64 + pch);
            cpa16(smaddr(&Vbuf[row * 72 + pch]), vbase0 + (size_t)row * 64 + pch);
        }
        if (tid < 16) cpa16(smaddr(&msb[tid * 4]), &mask[bS + tid * 4]);
        cpa_commit();
    }

    // Q fragments in registers for the whole kernel (2 m-tiles x 8 k-chunks)
    uint32_t qa[2][8][4];
    #pragma unroll
    for (int mt = 0; mt < 2; mt++) {
        const float* p0 = &qh[((size_t)bh * SEQ + q0 + wq + mt * 16 + q_) * 64];
        const float* p1 = p0 + 8 * 64;
        #pragma unroll
        for (int ksi = 0; ksi < 8; ksi++) {
            qa[mt][ksi][0] = __float_as_uint(p0[ksi * 8 + c_]);
            qa[mt][ksi][1] = __float_as_uint(p1[ksi * 8 + c_]);
            qa[mt][ksi][2] = __float_as_uint(p0[ksi * 8 + c_ + 4]);
            qa[mt][ksi][3] = __float_as_uint(p1[ksi * 8 + c_ + 4]);
        }
    }

    float mq[2][2];
    #pragma unroll
    for (int mt = 0; mt < 2; mt++) {
        mq[mt][0] = mask[bS + q0 + wq + mt * 16 + q_];
        mq[mt][1] = mask[bS + q0 + wq + mt * 16 + q_ + 8];
    }

    float l[2][2] = {};
    float o[2][8][4] = {};

    const int nT = SEQ / 64;   // 32
    for (int t = 0; t < nT; t++) {
        const int cur = t & 1;
        if (t + 1 < nT) {
            const int k0 = (t + 1) * 64;
            float* Kd = Kbuf + (cur ^ 1) * A_KS;
            float* Vd = Vbuf + (cur ^ 1) * A_VS;
            const float* kb = kbase0 + (size_t)k0 * 64;
            const float* vb = vbase0 + (size_t)k0 * 64;
            #pragma unroll
            for (int i = 0; i < 8; i++) {
                int row = prow + i * 8;
                cpa16(smaddr(&Kd[row * 68 + pch]), kb + (size_t)row * 64 + pch);
                cpa16(smaddr(&Vd[row * 72 + pch]), vb + (size_t)row * 64 + pch);
            }
            if (tid < 16) cpa16(smaddr(&msb[(cur ^ 1) * 64 + tid * 4]), &mask[bS + k0 + tid * 4]);
        }
        cpa_commit();
        cpa_wait1();
        __syncthreads();

        float* Kc = Kbuf + cur * A_KS;
        float* Vc = Vbuf + cur * A_VS;
        const float* mc = msb + cur * 64;

        // ---- S = Q K^T (warp: 32x64)
        float s[2][8][4] = {};
        #pragma unroll
        for (int ksi = 0; ksi < 8; ksi++) {
            #pragma unroll
            for (int nt = 0; nt < 8; nt++) {
                uint32_t b0 = __float_as_uint(Kc[(nt * 8 + q_) * 68 + ksi * 8 + c_]);
                uint32_t b1 = __float_as_uint(Kc[(nt * 8 + q_) * 68 + ksi * 8 + c_ + 4]);
                mma_tf32(s[0][nt], qa[0][ksi][0], qa[0][ksi][1], qa[0][ksi][2], qa[0][ksi][3], b0, b1);
                mma_tf32(s[1][nt], qa[1][ksi][0], qa[1][ksi][1], qa[1][ksi][2], qa[1][ksi][3], b0, b1);
            }
        }

        // ---- mask + exp2 (no max subtraction), accumulate row sums
        #pragma unroll
        for (int mt = 0; mt < 2; mt++) {
            #pragma unroll
            for (int nt = 0; nt < 8; nt++) {
                float mk0 = mc[nt * 8 + 2 * c_];
                float mk1 = mc[nt * 8 + 2 * c_ + 1];
                float e;
                e = mq[mt][0] * mk0; s[mt][nt][0] = fexp2(e * (s[mt][nt][0] * scale2) - (1.0f - e) * pen2);
                e = mq[mt][0] * mk1; s[mt][nt][1] = fexp2(e * (s[mt][nt][1] * scale2) - (1.0f - e) * pen2);
                e = mq[mt][1] * mk0; s[mt][nt][2] = fexp2(e * (s[mt][nt][2] * scale2) - (1.0f - e) * pen2);
                e = mq[mt][1] * mk1; s[mt][nt][3] = fexp2(e * (s[mt][nt][3] * scale2) - (1.0f - e) * pen2);
                l[mt][0] += s[mt][nt][0] + s[mt][nt][1];
                l[mt][1] += s[mt][nt][2] + s[mt][nt][3];
            }
        }

        // ---- P -> Ps (warp-private rows, stride 68 conflict-free for A reads)
        #pragma unroll
        for (int mt = 0; mt < 2; mt++) {
            int r = wq + mt * 16 + q_;
            #pragma unroll
            for (int nt = 0; nt < 8; nt++) {
                *(uint2*)&Ps[r * 68 + nt * 8 + 2 * c_] =
                    make_uint2(f2tf(s[mt][nt][0]), f2tf(s[mt][nt][1]));
                *(uint2*)&Ps[(r + 8) * 68 + nt * 8 + 2 * c_] =
                    make_uint2(f2tf(s[mt][nt][2]), f2tf(s[mt][nt][3]));
            }
        }
        __syncwarp();

        // ---- O += P V (warp: 32x64)
        #pragma unroll
        for (int ksi = 0; ksi < 8; ksi++) {
            uint32_t a[2][4];
            #pragma unroll
            for (int mt = 0; mt < 2; mt++) {
                int r = wq + mt * 16 + q_;
                a[mt][0] = __float_as_uint(Ps[r * 68 + ksi * 8 + c_]);
                a[mt][1] = __float_as_uint(Ps[(r + 8) * 68 + ksi * 8 + c_]);
                a[mt][2] = __float_as_uint(Ps[r * 68 + ksi * 8 + c_ + 4]);
                a[mt][3] = __float_as_uint(Ps[(r + 8) * 68 + ksi * 8 + c_ + 4]);
            }
            #pragma unroll
            for (int nt = 0; nt < 8; nt++) {
                uint32_t b0 = __float_as_uint(Vc[(ksi * 8 + c_) * 72 + nt * 8 + q_]);
                uint32_t b1 = __float_as_uint(Vc[(ksi * 8 + c_ + 4) * 72 + nt * 8 + q_]);
                mma_tf32(o[0][nt], a[0][0], a[0][1], a[0][2], a[0][3], b0, b1);
                mma_tf32(o[1][nt], a[1][0], a[1][1], a[1][2], a[1][3], b0, b1);
            }
        }
        __syncthreads();   // protect Kc/Vc/mc before next prefetch overwrites
    }

    // ---- final row-sum reduction over 4-lane group, normalize, write
    #pragma unroll
    for (int mt = 0; mt < 2; mt++) {
        #pragma unroll
        for (int half = 0; half < 2; half++) {
            l[mt][half] += __shfl_xor_sync(0xffffffffu, l[mt][half], 1);
            l[mt][half] += __shfl_xor_sync(0xffffffffu, l[mt][half], 2);
        }
    }

    #pragma unroll
    for (int mt = 0; mt < 2; mt++) {
        float inv0 = 1.0f / l[mt][0], inv1 = 1.0f / l[mt][1];
        int gr = bS + q0 + wq + mt * 16 + q_;
        #pragma unroll
        for (int nt = 0; nt < 8; nt++) {
            int col = h * DH + nt * 8 + 2 * c_;
            *(float2*)&ctx[(size_t)gr * HID + col] =
                make_float2(f2tf_f(o[mt][nt][0] * inv0), f2tf_f(o[mt][nt][1] * inv0));
            *(float2*)&ctx[(size_t)(gr + 8) * HID + col] =
                make_float2(f2tf_f(o[mt][nt][2] * inv1), f2tf_f(o[mt][nt][3] * inv1));
        }
    }
}

// ---------------------------------------------------------------------------
extern "C" void kernel_launch(void* const* d_in, const int* in_sizes, int n_in,
                              void* d_out, int out_size)
{
    const float* hs   = (const float*)d_in[0];
    const float* mask = (const float*)d_in[1];
    const float* Wq   = (const float*)d_in[2];
    const float* bq   = (const float*)d_in[3];
    const float* Wk   = (const float*)d_in[4];
    const float* bk   = (const float*)d_in[5];
    const float* Wv   = (const float*)d_in[6];
    const float* bv   = (const float*)d_in[7];
    const float* Wo   = (const float*)d_in[8];
    const float* bo   = (const float*)d_in[9];
    float* out = (float*)d_out;

    float *hsr, *wr, *qh, *kh, *vh, *cb;
    cudaGetSymbolAddress((void**)&hsr, g_hsr);
    cudaGetSymbolAddress((void**)&wr,  g_wr);
    cudaGetSymbolAddress((void**)&qh,  g_qh);
    cudaGetSymbolAddress((void**)&kh,  g_kh);
    cudaGetSymbolAddress((void**)&vh,  g_vh);
    cudaGetSymbolAddress((void**)&cb,  g_ctx);

    cudaFuncSetAttribute(gemm4_qkv,         cudaFuncAttributeMaxDynamicSharedMemorySize, G_SMEM_BYTES);
    cudaFuncSetAttribute(gemm4<true,false>, cudaFuncAttributeMaxDynamicSharedMemorySize, G_SMEM_BYTES);
    cudaFuncSetAttribute(attn5,             cudaFuncAttributeMaxDynamicSharedMemorySize, A_SMEM_BYTES);

    // --- pre-round inputs to tf32 ---
    round_hs<<<(MTOT * HID / 4 + 255) / 256, 256>>>(hs, hsr, MTOT * HID / 4);
    dim3 wgrid((HID * HID / 4 + 255) / 256, 4);
    round_w4<<<wgrid, 256>>>(Wq, Wk, Wv, Wo, wr);

    // --- fused QKV projections (write head-major rounded) ---
    dim3 qkvgrid(HID / 128, MTOT / 128, 3);   // (6, 64, 3)
    gemm4_qkv<<<qkvgrid, 128, G_SMEM_BYTES>>>(
        hsr,
        wr + 0 * (size_t)HID * HID, wr + 1 * (size_t)HID * HID, wr + 2 * (size_t)HID * HID,
        bq, bk, bv, qh, kh, vh);

    // --- attention ---
    dim3 agrid(SEQ / 128, NH, BATCH);    // (16, 12, 4) = 768 blocks
    attn5<<<agrid, 128, A_SMEM_BYTES>>>(qh, kh, vh, mask, cb);

    // --- output projection + GELU ---
    dim3 ggrid(HID / 128, MTOT / 128);   // (6, 64)
    gemm4<true,false><<<ggrid, 128, G_SMEM_BYTES>>>(cb, wr + 3 * (size_t)HID * HID, bo, out);
}